// round 5
// baseline (speedup 1.0000x reference)
#include <cuda_runtime.h>
#include <math.h>

// Problem constants
#define BB 8
#define TT 96
#define NN 20000
#define PP 12
#define LL 3
#define DD 32
#define CC 128
#define MM 64
#define RTOT (BB*NN)          // 160000 rows
#define NCH 40                // node chunks for kv/ksum partials
#define CHSZ (NN/NCH)         // 500

#define SFAC 0.4204482076268573f   // 32^{-1/4}
#define RATIO 0.125f               // 1/sqrt(64)
#define EPSRF 1e-6f

// ---------------- device scratch (static globals: allocation-free) ----------
__device__ float g_h   [(size_t)BB*NN*CC];
__device__ float g_skip[(size_t)BB*NN*CC];
__device__ float g_u   [(size_t)BB*NN*CC];
__device__ float g_phiq[(size_t)BB*NN*MM];
__device__ float g_phik[(size_t)BB*NN*MM];
__device__ float g_A1[NN*DD];
__device__ float g_A2[NN*DD];
__device__ float g_c1[BB*DD];
__device__ float g_c2[BB*DD];
__device__ float g_Pc2[BB*MM];
__device__ float g_mark[BB*DD];
__device__ float g_tvv[BB*DD];
__device__ float g_wvv[BB*DD];
__device__ float g_colmax[MM];
__device__ float g_stabk[BB];
__device__ float g_kvpart[(size_t)BB*NCH*MM*CC];
__device__ float g_kv[BB*MM*CC];
__device__ float g_kspart[BB*NCH*MM];
__device__ float g_ksum[BB*MM];
__device__ float g_den[BB*NN];

// ---------------- per-batch constants -----------------
__global__ void k_const(const float* __restrict__ xmark,
                        const float* __restrict__ time_tab,
                        const float* __restrict__ week_tab,
                        const float* __restrict__ input_w,
                        const float* __restrict__ input_b,
                        const float* __restrict__ w1_w, const float* __restrict__ w1_b,
                        const float* __restrict__ w2_w, const float* __restrict__ w2_b,
                        const float* __restrict__ proj)
{
    int b = blockIdx.x, t = threadIdx.x;
    __shared__ float xm0[TT], xm1[TT], stv[DD], swv[DD], sc1[DD], sc2[DD];

    float m0 = xmark[(b*TT + (TT-1))*2 + 0];
    float m1 = xmark[(b*TT + (TT-1))*2 + 1];
    int tod = (int)(m0 * (float)TT); tod = min(max(tod, 0), TT-1);
    int dow = (int)(m1 * 7.0f);      dow = min(max(dow, 0), 6);

    if (t < TT) { xm0[t] = xmark[(b*TT+t)*2]; xm1[t] = xmark[(b*TT+t)*2+1]; }
    if (t < DD) {
        float tv = time_tab[tod*DD+t], wv = week_tab[dow*DD+t];
        stv[t] = tv; swv[t] = wv;
        g_tvv[b*DD+t] = tv; g_wvv[b*DD+t] = wv;
    }
    __syncthreads();
    if (t < DD) {
        float mc = input_b[t];
        for (int k = 0; k < TT; k++)
            mc += xm0[k]*input_w[t*(3*TT)+TT+k] + xm1[k]*input_w[t*(3*TT)+2*TT+k];
        g_mark[b*DD+t] = mc;
        float v1 = w1_b[t], v2 = w2_b[t];
        for (int g = 0; g < DD; g++) {
            v1 += stv[g]*w1_w[t*(3*DD)+DD+g] + swv[g]*w1_w[t*(3*DD)+2*DD+g];
            v2 += stv[g]*w2_w[t*(3*DD)+DD+g] + swv[g]*w2_w[t*(3*DD)+2*DD+g];
        }
        v1 *= 2.0f; v2 *= 2.0f;                  // 1/sqrt(tau) = 2
        sc1[t] = v1; sc2[t] = v2;
        g_c1[b*DD+t] = v1; g_c2[b*DD+t] = v2;
    }
    __syncthreads();
    if (t < MM) {
        float p = 0.f;
        #pragma unroll
        for (int c = 0; c < DD; c++) p += sc2[c]*proj[t*DD+c];
        g_Pc2[b*MM+t] = SFAC * p;
    }
}

// ---------------- node-dependent parts of nv1/nv2 ----------------
__global__ void k_node(const float* __restrict__ node_emb,
                       const float* __restrict__ w1_w,
                       const float* __restrict__ w2_w)
{
    __shared__ float w1s[DD*DD], w2s[DD*DD];
    int t = threadIdx.x;
    for (int i = t; i < DD*DD; i += 256) {
        int c = i / DD, g = i % DD;
        w1s[i] = w1_w[c*(3*DD)+g];
        w2s[i] = w2_w[c*(3*DD)+g];
    }
    __syncthreads();
    int n = blockIdx.x*256 + t;
    if (n >= NN) return;
    float ne[DD];
    #pragma unroll
    for (int g = 0; g < DD; g++) ne[g] = node_emb[n*DD+g];
    #pragma unroll 4
    for (int c = 0; c < DD; c++) {
        float a1 = 0.f, a2 = 0.f;
        #pragma unroll
        for (int g = 0; g < DD; g++) { a1 += ne[g]*w1s[c*DD+g]; a2 += ne[g]*w2s[c*DD+g]; }
        g_A1[n*DD+c] = 2.0f*a1;
        g_A2[n*DD+c] = 2.0f*a2;
    }
}

// ---------------- per-feature max over nodes of s * A2 . proj[m] -----------
__global__ void k_colmax(const float* __restrict__ proj)
{
    int m = blockIdx.x, t = threadIdx.x;
    __shared__ float pr[DD];
    __shared__ float red[8];
    if (t < DD) pr[t] = proj[m*DD+t];
    __syncthreads();
    float mx = -1e30f;
    for (int n = t; n < NN; n += 256) {
        float d = 0.f;
        #pragma unroll
        for (int c = 0; c < DD; c++) d += g_A2[n*DD+c]*pr[c];
        mx = fmaxf(mx, d);
    }
    for (int o = 16; o; o >>= 1) mx = fmaxf(mx, __shfl_down_sync(0xffffffffu, mx, o));
    if ((t & 31) == 0) red[t >> 5] = mx;
    __syncthreads();
    if (t == 0) {
        float r = red[0];
        for (int w = 1; w < 8; w++) r = fmaxf(r, red[w]);
        g_colmax[m] = SFAC * r;
    }
}

__global__ void k_stab()
{
    int b = blockIdx.x, t = threadIdx.x;     // 64 threads
    __shared__ float red[2];
    float v = g_colmax[t] + g_Pc2[b*MM+t];
    for (int o = 16; o; o >>= 1) v = fmaxf(v, __shfl_down_sync(0xffffffffu, v, o));
    if ((t & 31) == 0) red[t >> 5] = v;
    __syncthreads();
    if (t == 0) g_stabk[b] = fmaxf(red[0], red[1]);
}

// ---------------- FAVOR+ random features ----------------
__global__ void k_phi(const float* __restrict__ proj)
{
    int b = blockIdx.y, t = threadIdx.x;
    __shared__ float ps[MM*DD], c1s[DD], c2s[DD];
    for (int i = t; i < MM*DD; i += 128) ps[i] = proj[i];
    if (t < DD) { c1s[t] = g_c1[b*DD+t]; c2s[t] = g_c2[b*DD+t]; }
    __syncthreads();
    int n = blockIdx.x*128 + t;
    if (n >= NN) return;

    float nv[DD]; float sq = 0.f;
    #pragma unroll
    for (int c = 0; c < DD; c++) { float v = g_A1[n*DD+c] + c1s[c]; nv[c] = v; sq += v*v; }
    float diag = 0.5f*SFAC*SFAC*sq;
    float mx = -1e30f;
    for (int m = 0; m < MM; m++) {
        float d = 0.f;
        #pragma unroll
        for (int c = 0; c < DD; c++) d += nv[c]*ps[m*DD+c];
        mx = fmaxf(mx, SFAC*d);
    }
    size_t base = ((size_t)(b*NN) + n) * MM;
    for (int m = 0; m < MM; m++) {
        float d = 0.f;
        #pragma unroll
        for (int c = 0; c < DD; c++) d += nv[c]*ps[m*DD+c];
        g_phiq[base+m] = RATIO * (expf(SFAC*d - diag - mx) + EPSRF);
    }
    // keys
    sq = 0.f;
    #pragma unroll
    for (int c = 0; c < DD; c++) { float v = g_A2[n*DD+c] + c2s[c]; nv[c] = v; sq += v*v; }
    diag = 0.5f*SFAC*SFAC*sq;
    float stab = g_stabk[b];
    for (int m = 0; m < MM; m++) {
        float d = 0.f;
        #pragma unroll
        for (int c = 0; c < DD; c++) d += nv[c]*ps[m*DD+c];
        g_phik[base+m] = RATIO * (expf(SFAC*d - diag - stab) + EPSRF);
    }
}

// ---------------- input embedding + h/skip assembly ----------------
__global__ void k_input(const float* __restrict__ x,
                        const float* __restrict__ input_w,
                        const float* __restrict__ node_emb)
{
    int b = blockIdx.y, t = threadIdx.x;
    __shared__ float wts[TT*DD];
    __shared__ float mk[DD], tv[DD], wv[DD];
    for (int i = t; i < TT*DD; i += 128) {
        int tt = i / DD, c = i % DD;
        wts[i] = input_w[c*(3*TT)+tt];
    }
    if (t < DD) { mk[t] = g_mark[b*DD+t]; tv[t] = g_tvv[b*DD+t]; wv[t] = g_wvv[b*DD+t]; }
    __syncthreads();
    int n = blockIdx.x*128 + t;
    if (n >= NN) return;
    float acc[DD];
    #pragma unroll
    for (int c = 0; c < DD; c++) acc[c] = mk[c];
    for (int tt = 0; tt < TT; tt++) {
        float xv = x[((size_t)b*TT + tt)*NN + n];
        #pragma unroll
        for (int c = 0; c < DD; c++) acc[c] += xv * wts[tt*DD+c];
    }
    size_t base = ((size_t)(b*NN) + n) * CC;
    #pragma unroll
    for (int c = 0; c < DD; c++) { g_h[base+c] = acc[c]; g_skip[base+c] = acc[c]; }
    #pragma unroll
    for (int c = 0; c < DD; c++) { float v = node_emb[n*DD+c]; g_h[base+DD+c] = v; g_skip[base+DD+c] = v; }
    #pragma unroll
    for (int c = 0; c < DD; c++) { g_h[base+2*DD+c] = tv[c]; g_skip[base+2*DD+c] = tv[c]; }
    #pragma unroll
    for (int c = 0; c < DD; c++) { g_h[base+3*DD+c] = wv[c]; g_skip[base+3*DD+c] = wv[c]; }
}

// ---------------- ksum = sum_n phi_k (deterministic chunked) ----------------
__global__ void k_ksum()
{
    int ch = blockIdx.x, b = blockIdx.y, t = threadIdx.x; // 256 thr
    int m = t & 63, sub = t >> 6;
    int n0 = ch*CHSZ;
    float acc = 0.f;
    for (int n = n0 + sub; n < n0 + CHSZ; n += 4)
        acc += g_phik[((size_t)(b*NN) + n)*MM + m];
    __shared__ float red[256];
    red[t] = acc;
    __syncthreads();
    if (t < 64)
        g_kspart[(b*NCH+ch)*MM + m] = red[m] + red[64+m] + red[128+m] + red[192+m];
}

__global__ void k_ksumred()
{
    int b = blockIdx.x, m = threadIdx.x;   // 64 threads
    float s = 0.f;
    for (int ch = 0; ch < NCH; ch++) s += g_kspart[(b*NCH+ch)*MM + m];
    g_ksum[b*MM+m] = s;
}

__global__ void k_den()
{
    int b = blockIdx.y, t = threadIdx.x;
    __shared__ float ks[MM];
    if (t < MM) ks[t] = g_ksum[b*MM+t];
    __syncthreads();
    int n = blockIdx.x*128 + t;
    if (n >= NN) return;
    size_t base = ((size_t)(b*NN) + n)*MM;
    float d = 0.f;
    #pragma unroll
    for (int m = 0; m < MM; m++) d += g_phiq[base+m]*ks[m];
    g_den[b*NN+n] = d;
}

// ---------------- gating GEMMs: u = sigmoid(h@Wi^T+bi) * (h@Wo^T+bo) --------
// 128-row x 128-col tile, 512 threads, per-thread 8r x 4c x 2 mats.
__global__ __launch_bounds__(512) void k_gate(const float* __restrict__ in_w,
                                              const float* __restrict__ in_b,
                                              const float* __restrict__ out_w,
                                              const float* __restrict__ out_b,
                                              int layer)
{
    __shared__ float hs[32*128];
    __shared__ float wi[32*128];
    __shared__ float wo[32*128];
    int t = threadIdx.x;
    int cg = t & 31;        // col group: cols cg*4..+3
    int rg = t >> 5;        // row group: rows rg*8..+7 (0..15)
    size_t rowBase = (size_t)blockIdx.x * 128;
    const float* IW = in_w  + (size_t)layer*CC*CC;
    const float* OW = out_w + (size_t)layer*CC*CC;

    float ai[8][4], ao[8][4];
    #pragma unroll
    for (int a = 0; a < 8; a++)
        #pragma unroll
        for (int q = 0; q < 4; q++) { ai[a][q] = 0.f; ao[a][q] = 0.f; }

    for (int kc = 0; kc < 4; kc++) {
        #pragma unroll
        for (int L = 0; L < 2; L++) {
            int lin = t*2 + L;                // 0..1023
            int row = lin >> 3, q = lin & 7;  // row 0..127, q 0..7
            int ko = kc*32 + q*4;
            float4 hv  = *(const float4*)&g_h[(rowBase+row)*CC + ko];
            float4 wiv = *(const float4*)&IW[(size_t)row*CC + ko];
            float4 wov = *(const float4*)&OW[(size_t)row*CC + ko];
            hs[(q*4+0)*128+row]=hv.x;  hs[(q*4+1)*128+row]=hv.y;
            hs[(q*4+2)*128+row]=hv.z;  hs[(q*4+3)*128+row]=hv.w;
            wi[(q*4+0)*128+row]=wiv.x; wi[(q*4+1)*128+row]=wiv.y;
            wi[(q*4+2)*128+row]=wiv.z; wi[(q*4+3)*128+row]=wiv.w;
            wo[(q*4+0)*128+row]=wov.x; wo[(q*4+1)*128+row]=wov.y;
            wo[(q*4+2)*128+row]=wov.z; wo[(q*4+3)*128+row]=wov.w;
        }
        __syncthreads();
        #pragma unroll
        for (int j = 0; j < 32; j++) {
            float4 r0 = *(float4*)&hs[j*128 + rg*8];
            float4 r1 = *(float4*)&hs[j*128 + rg*8 + 4];
            float4 vi = *(float4*)&wi[j*128 + cg*4];
            float4 vo = *(float4*)&wo[j*128 + cg*4];
            float rrv[8] = {r0.x,r0.y,r0.z,r0.w,r1.x,r1.y,r1.z,r1.w};
            float vvi[4] = {vi.x,vi.y,vi.z,vi.w};
            float vvo[4] = {vo.x,vo.y,vo.z,vo.w};
            #pragma unroll
            for (int a = 0; a < 8; a++)
                #pragma unroll
                for (int q = 0; q < 4; q++) {
                    ai[a][q] += rrv[a]*vvi[q];
                    ao[a][q] += rrv[a]*vvo[q];
                }
        }
        __syncthreads();
    }
    float bi[4], bo[4];
    #pragma unroll
    for (int q = 0; q < 4; q++) {
        bi[q] = in_b [layer*CC + cg*4 + q];
        bo[q] = out_b[layer*CC + cg*4 + q];
    }
    #pragma unroll
    for (int a = 0; a < 8; a++) {
        size_t row = rowBase + rg*8 + a;
        float4 uv;
        float s0 = 1.0f/(1.0f+expf(-(ai[a][0]+bi[0])));
        float s1 = 1.0f/(1.0f+expf(-(ai[a][1]+bi[1])));
        float s2 = 1.0f/(1.0f+expf(-(ai[a][2]+bi[2])));
        float s3 = 1.0f/(1.0f+expf(-(ai[a][3]+bi[3])));
        uv.x = s0*(ao[a][0]+bo[0]);
        uv.y = s1*(ao[a][1]+bo[1]);
        uv.z = s2*(ao[a][2]+bo[2]);
        uv.w = s3*(ao[a][3]+bo[3]);
        *(float4*)&g_u[row*CC + cg*4] = uv;
    }
}

// ---------------- kv partials: kv[m][c] = sum_n phik[n][m] * u[n][c] --------
__global__ void k_kv()
{
    int ch = blockIdx.x, b = blockIdx.y, t = threadIdx.x;  // 128 threads
    __shared__ float phs[4*64];
    __shared__ float us[4*128];
    int mb = (t & 7)*8, cb = (t >> 3)*8;
    float acc[8][8];
    #pragma unroll
    for (int i = 0; i < 8; i++)
        #pragma unroll
        for (int j = 0; j < 8; j++) acc[i][j] = 0.f;
    int n0 = ch*CHSZ;
    for (int it = 0; it < CHSZ/4; it++) {
        int nb = n0 + it*4;
        __syncthreads();
        #pragma unroll
        for (int k = 0; k < 6; k++) {
            int lin = t + k*128;
            if (lin < 256) {
                int nn = lin >> 6, m = lin & 63;
                phs[nn*64+m] = g_phik[((size_t)(b*NN) + nb + nn)*MM + m];
            } else {
                int l2 = lin - 256;
                int nn = l2 >> 7, c = l2 & 127;
                us[nn*128+c] = g_u[((size_t)(b*NN) + nb + nn)*CC + c];
            }
        }
        __syncthreads();
        #pragma unroll
        for (int nn = 0; nn < 4; nn++) {
            float4 p0 = *(float4*)&phs[nn*64+mb];
            float4 p1 = *(float4*)&phs[nn*64+mb+4];
            float4 u0 = *(float4*)&us[nn*128+cb];
            float4 u1 = *(float4*)&us[nn*128+cb+4];
            float pm[8] = {p0.x,p0.y,p0.z,p0.w,p1.x,p1.y,p1.z,p1.w};
            float uc[8] = {u0.x,u0.y,u0.z,u0.w,u1.x,u1.y,u1.z,u1.w};
            #pragma unroll
            for (int i = 0; i < 8; i++)
                #pragma unroll
                for (int j = 0; j < 8; j++) acc[i][j] += pm[i]*uc[j];
        }
    }
    float* dst = &g_kvpart[((size_t)(b*NCH) + ch)*MM*CC];
    #pragma unroll
    for (int i = 0; i < 8; i++) {
        float4 v0 = make_float4(acc[i][0],acc[i][1],acc[i][2],acc[i][3]);
        float4 v1 = make_float4(acc[i][4],acc[i][5],acc[i][6],acc[i][7]);
        *(float4*)&dst[(mb+i)*CC + cb]     = v0;
        *(float4*)&dst[(mb+i)*CC + cb + 4] = v1;
    }
}

__global__ void k_kvred()
{
    int b = blockIdx.x, t = threadIdx.x;   // 256 threads
    for (int i = t; i < MM*CC; i += 256) {
        float s = 0.f;
        for (int ch = 0; ch < NCH; ch++)
            s += g_kvpart[((size_t)(b*NCH) + ch)*MM*CC + i];
        g_kv[b*MM*CC + i] = s;
    }
}

// ---------------- num + divide + residual + layernorm (in place on g_h) ----
__global__ void k_num(const float* __restrict__ ln_g,
                      const float* __restrict__ ln_b,
                      int layer)
{
    int b = blockIdx.y, t = threadIdx.x;   // 128 threads, t = channel
    __shared__ float kvs[MM*CC];           // 32 KB
    __shared__ float phs[8*64];
    __shared__ float red1[4], red2[4];
    for (int i = t; i < MM*CC; i += 128) kvs[i] = g_kv[b*MM*CC + i];
    float gam = ln_g[layer*CC + t], bet = ln_b[layer*CC + t];
    int nbase = blockIdx.x*64;
    int lane = t & 31, w = t >> 5;
    for (int it = 0; it < 8; it++) {
        int r0 = nbase + it*8;
        __syncthreads();
        #pragma unroll
        for (int k = 0; k < 4; k++) {
            int lin = t + k*128;
            int rr = lin >> 6, m = lin & 63;
            int n = r0 + rr;
            phs[lin] = (n < NN) ? g_phiq[((size_t)(b*NN) + n)*MM + m] : 0.f;
        }
        __syncthreads();
        float acc[8];
        #pragma unroll
        for (int rr = 0; rr < 8; rr++) acc[rr] = 0.f;
        for (int m = 0; m < MM; m++) {
            float kvv = kvs[m*CC + t];
            #pragma unroll
            for (int rr = 0; rr < 8; rr++) acc[rr] += phs[rr*64+m]*kvv;
        }
        for (int rr = 0; rr < 8; rr++) {
            int n = r0 + rr;
            float val = 0.f;
            size_t idx = ((size_t)(b*NN) + n)*CC + t;
            if (n < NN) val = acc[rr]/g_den[b*NN+n] + g_h[idx];
            float s = val;
            for (int o = 16; o; o >>= 1) s += __shfl_down_sync(0xffffffffu, s, o);
            if (lane == 0) red1[w] = s;
            __syncthreads();
            float mu = (red1[0]+red1[1]+red1[2]+red1[3]) * (1.0f/128.0f);
            float d = val - mu;
            float s2 = d*d;
            for (int o = 16; o; o >>= 1) s2 += __shfl_down_sync(0xffffffffu, s2, o);
            if (lane == 0) red2[w] = s2;
            __syncthreads();
            float var = (red2[0]+red2[1]+red2[2]+red2[3]) * (1.0f/128.0f);
            if (n < NN) g_h[idx] = d * rsqrtf(var + 1e-5f) * gam + bet;
            __syncthreads();
        }
    }
}

// ---------------- regression head ----------------
__global__ void k_reg(const float* __restrict__ reg_w,
                      const float* __restrict__ reg_b,
                      float* __restrict__ out)
{
    int b = blockIdx.y, t = threadIdx.x;   // 128 threads, t = local node
    __shared__ float rw[PP*2*CC];          // 12 KB
    __shared__ float st[128*33];           // padded transpose tile
    for (int i = t; i < PP*2*CC; i += 128) rw[i] = reg_w[i];
    int nbase = blockIdx.x*128;
    float acc[PP];
    #pragma unroll
    for (int p = 0; p < PP; p++) acc[p] = 0.f;
    for (int src = 0; src < 2; src++) {
        const float* S = src ? g_h : g_skip;
        for (int c0 = 0; c0 < CC; c0 += 32) {
            __syncthreads();
            #pragma unroll
            for (int k = 0; k < 32; k++) {
                int lin = t + k*128;
                int rr = lin >> 5, cc = lin & 31;
                int n = nbase + rr;
                st[rr*33+cc] = (n < NN) ? S[((size_t)(b*NN) + n)*CC + c0 + cc] : 0.f;
            }
            __syncthreads();
            #pragma unroll
            for (int cc = 0; cc < 32; cc++) {
                float v = st[t*33+cc];
                #pragma unroll
                for (int p = 0; p < PP; p++)
                    acc[p] += v * rw[p*(2*CC) + src*CC + c0 + cc];
            }
        }
    }
    int n = nbase + t;
    if (n < NN) {
        #pragma unroll
        for (int p = 0; p < PP; p++)
            out[((size_t)(b*PP) + p)*NN + n] = acc[p] + reg_b[p];
    }
}

// ---------------- launcher ----------------
extern "C" void kernel_launch(void* const* d_in, const int* in_sizes, int n_in,
                              void* d_out, int out_size)
{
    const float* x        = (const float*)d_in[0];
    const float* xmark    = (const float*)d_in[1];
    const float* node_emb = (const float*)d_in[2];
    const float* time_tab = (const float*)d_in[3];
    const float* week_tab = (const float*)d_in[4];
    const float* input_w  = (const float*)d_in[5];
    const float* input_b  = (const float*)d_in[6];
    const float* w1_w     = (const float*)d_in[7];
    const float* w1_b     = (const float*)d_in[8];
    const float* w2_w     = (const float*)d_in[9];
    const float* w2_b     = (const float*)d_in[10];
    const float* in_w     = (const float*)d_in[11];
    const float* in_b     = (const float*)d_in[12];
    const float* out_w    = (const float*)d_in[13];
    const float* out_b    = (const float*)d_in[14];
    const float* ln_g     = (const float*)d_in[15];
    const float* ln_b     = (const float*)d_in[16];
    const float* reg_w    = (const float*)d_in[17];
    const float* reg_b    = (const float*)d_in[18];
    const float* proj     = (const float*)d_in[19];
    float* out = (float*)d_out;

    dim3 gBN((NN + 127)/128, BB);

    k_const<<<BB, 128>>>(xmark, time_tab, week_tab, input_w, input_b,
                         w1_w, w1_b, w2_w, w2_b, proj);
    k_node<<<(NN + 255)/256, 256>>>(node_emb, w1_w, w2_w);
    k_colmax<<<MM, 256>>>(proj);
    k_stab<<<BB, 64>>>();
    k_phi<<<gBN, 128>>>(proj);
    k_input<<<gBN, 128>>>(x, input_w, node_emb);
    k_ksum<<<dim3(NCH, BB), 256>>>();
    k_ksumred<<<BB, 64>>>();
    k_den<<<gBN, 128>>>();

    for (int l = 0; l < LL; l++) {
        k_gate<<<RTOT/128, 512>>>(in_w, in_b, out_w, out_b, l);
        k_kv<<<dim3(NCH, BB), 128>>>();
        k_kvred<<<BB, 256>>>();
        k_num<<<dim3((NN + 63)/64, BB), 128>>>(ln_g, ln_b, l);
    }
    k_reg<<<gBN, 128>>>(reg_w, reg_b, out);
}

// round 7
// speedup vs baseline: 1.3962x; 1.3962x over previous
#include <cuda_runtime.h>
#include <math.h>

// Problem constants
#define BB 8
#define TT 96
#define NN 20000
#define PP 12
#define LL 3
#define DD 32
#define CC 128
#define MM 64
#define RTOT (BB*NN)          // 160000 rows
#define NCH 100               // node chunks for kv/ksum partials
#define CHSZ (NN/NCH)         // 200

#define SFAC 0.4204482076268573f   // 32^{-1/4}
#define RATIO 0.125f               // 1/sqrt(64)
#define EPSRF 1e-6f

typedef unsigned long long ull;

// ---- packed fp32x2 helpers (SASS FFMA2 — only reachable via PTX) ----
__device__ __forceinline__ ull splat2(float v){
    ull r; asm("mov.b64 %0, {%1, %1};" : "=l"(r) : "f"(v)); return r;
}
__device__ __forceinline__ void fma2(ull& acc, ull a, ull b){
    asm("fma.rn.f32x2 %0, %1, %2, %0;" : "+l"(acc) : "l"(a), "l"(b));
}
__device__ __forceinline__ float2 unpack2(ull v){
    float2 f; asm("mov.b64 {%0, %1}, %2;" : "=f"(f.x), "=f"(f.y) : "l"(v)); return f;
}

// ---------------- device scratch (static globals: allocation-free) ----------
__device__ float g_h   [(size_t)BB*NN*CC];
__device__ float g_skip[(size_t)BB*NN*CC];
__device__ float g_u   [(size_t)BB*NN*CC];
__device__ float g_phiq[(size_t)BB*NN*MM];
__device__ float g_phik[(size_t)BB*NN*MM];
__device__ float g_A1[NN*DD];
__device__ float g_A2[NN*DD];
__device__ float g_c1[BB*DD];
__device__ float g_c2[BB*DD];
__device__ float g_Pc2[BB*MM];
__device__ float g_mark[BB*DD];
__device__ float g_tvv[BB*DD];
__device__ float g_wvv[BB*DD];
__device__ float g_colmax[MM];
__device__ float g_stabk[BB];
__device__ float g_kvpart[(size_t)BB*NCH*MM*CC];
__device__ float g_kv[BB*MM*CC];
__device__ float g_kspart[BB*NCH*MM];
__device__ float g_ksum[BB*MM];
__device__ float g_den[BB*NN];

// ---------------- per-batch constants -----------------
__global__ void k_const(const float* __restrict__ xmark,
                        const float* __restrict__ time_tab,
                        const float* __restrict__ week_tab,
                        const float* __restrict__ input_w,
                        const float* __restrict__ input_b,
                        const float* __restrict__ w1_w, const float* __restrict__ w1_b,
                        const float* __restrict__ w2_w, const float* __restrict__ w2_b,
                        const float* __restrict__ proj)
{
    int b = blockIdx.x, t = threadIdx.x;
    __shared__ float xm0[TT], xm1[TT], stv[DD], swv[DD], sc1[DD], sc2[DD];

    float m0 = xmark[(b*TT + (TT-1))*2 + 0];
    float m1 = xmark[(b*TT + (TT-1))*2 + 1];
    int tod = (int)(m0 * (float)TT); tod = min(max(tod, 0), TT-1);
    int dow = (int)(m1 * 7.0f);      dow = min(max(dow, 0), 6);

    if (t < TT) { xm0[t] = xmark[(b*TT+t)*2]; xm1[t] = xmark[(b*TT+t)*2+1]; }
    if (t < DD) {
        float tv = time_tab[tod*DD+t], wv = week_tab[dow*DD+t];
        stv[t] = tv; swv[t] = wv;
        g_tvv[b*DD+t] = tv; g_wvv[b*DD+t] = wv;
    }
    __syncthreads();
    if (t < DD) {
        float mc = input_b[t];
        for (int k = 0; k < TT; k++)
            mc += xm0[k]*input_w[t*(3*TT)+TT+k] + xm1[k]*input_w[t*(3*TT)+2*TT+k];
        g_mark[b*DD+t] = mc;
        float v1 = w1_b[t], v2 = w2_b[t];
        for (int g = 0; g < DD; g++) {
            v1 += stv[g]*w1_w[t*(3*DD)+DD+g] + swv[g]*w1_w[t*(3*DD)+2*DD+g];
            v2 += stv[g]*w2_w[t*(3*DD)+DD+g] + swv[g]*w2_w[t*(3*DD)+2*DD+g];
        }
        v1 *= 2.0f; v2 *= 2.0f;                  // 1/sqrt(tau) = 2
        sc1[t] = v1; sc2[t] = v2;
        g_c1[b*DD+t] = v1; g_c2[b*DD+t] = v2;
    }
    __syncthreads();
    if (t < MM) {
        float p = 0.f;
        #pragma unroll
        for (int c = 0; c < DD; c++) p += sc2[c]*proj[t*DD+c];
        g_Pc2[b*MM+t] = SFAC * p;
    }
}

// ---------------- node-dependent parts of nv1/nv2 ----------------
__global__ void k_node(const float* __restrict__ node_emb,
                       const float* __restrict__ w1_w,
                       const float* __restrict__ w2_w)
{
    __shared__ float w1s[DD*DD], w2s[DD*DD];
    int t = threadIdx.x;
    for (int i = t; i < DD*DD; i += 256) {
        int c = i / DD, g = i % DD;
        w1s[i] = w1_w[c*(3*DD)+g];
        w2s[i] = w2_w[c*(3*DD)+g];
    }
    __syncthreads();
    int n = blockIdx.x*256 + t;
    if (n >= NN) return;
    float ne[DD];
    #pragma unroll
    for (int g = 0; g < DD; g++) ne[g] = node_emb[n*DD+g];
    #pragma unroll 4
    for (int c = 0; c < DD; c++) {
        float a1 = 0.f, a2 = 0.f;
        #pragma unroll
        for (int g = 0; g < DD; g++) { a1 += ne[g]*w1s[c*DD+g]; a2 += ne[g]*w2s[c*DD+g]; }
        g_A1[n*DD+c] = 2.0f*a1;
        g_A2[n*DD+c] = 2.0f*a2;
    }
}

// ---------------- per-feature max over nodes of s * A2 . proj[m] -----------
__global__ void k_colmax(const float* __restrict__ proj)
{
    int m = blockIdx.x, t = threadIdx.x;
    __shared__ float pr[DD];
    __shared__ float red[8];
    if (t < DD) pr[t] = proj[m*DD+t];
    __syncthreads();
    float mx = -1e30f;
    for (int n = t; n < NN; n += 256) {
        float d = 0.f;
        #pragma unroll
        for (int c = 0; c < DD; c++) d += g_A2[n*DD+c]*pr[c];
        mx = fmaxf(mx, d);
    }
    for (int o = 16; o; o >>= 1) mx = fmaxf(mx, __shfl_down_sync(0xffffffffu, mx, o));
    if ((t & 31) == 0) red[t >> 5] = mx;
    __syncthreads();
    if (t == 0) {
        float r = red[0];
        for (int w = 1; w < 8; w++) r = fmaxf(r, red[w]);
        g_colmax[m] = SFAC * r;
    }
}

__global__ void k_stab()
{
    int b = blockIdx.x, t = threadIdx.x;     // 64 threads
    __shared__ float red[2];
    float v = g_colmax[t] + g_Pc2[b*MM+t];
    for (int o = 16; o; o >>= 1) v = fmaxf(v, __shfl_down_sync(0xffffffffu, v, o));
    if ((t & 31) == 0) red[t >> 5] = v;
    __syncthreads();
    if (t == 0) g_stabk[b] = fmaxf(red[0], red[1]);
}

// ---------------- FAVOR+ random features (dash in regs, f32x2, __expf) -----
__global__ __launch_bounds__(128) void k_phi(const float* __restrict__ proj)
{
    int b = blockIdx.y, t = threadIdx.x;
    __shared__ float psT[DD*MM];              // transposed: [c][m]
    __shared__ float c1s[DD], c2s[DD];
    for (int i = t; i < DD*MM; i += 128) {
        int m = i >> 5, c = i & 31;
        psT[c*MM+m] = proj[m*DD+c];
    }
    if (t < DD) { c1s[t] = g_c1[b*DD+t]; c2s[t] = g_c2[b*DD+t]; }
    __syncthreads();
    int n = blockIdx.x*128 + t;
    if (n >= NN) return;

    size_t base = ((size_t)(b*NN) + n) * MM;
    ull dd[32];
    float nv[DD];

    // ---- queries ----
    float sq = 0.f;
    #pragma unroll
    for (int c = 0; c < DD; c++) { float v = SFAC*(g_A1[n*DD+c] + c1s[c]); nv[c] = v; sq += v*v; }
    float diag = 0.5f*sq;
    #pragma unroll
    for (int i = 0; i < 32; i++) dd[i] = 0ull;
    #pragma unroll 4
    for (int c = 0; c < DD; c++) {
        ull s = splat2(nv[c]);
        const ulonglong2* pp = (const ulonglong2*)&psT[c*MM];
        #pragma unroll
        for (int i = 0; i < 16; i++) {
            ulonglong2 pv = pp[i];
            fma2(dd[2*i],   s, pv.x);
            fma2(dd[2*i+1], s, pv.y);
        }
    }
    float mx = -1e30f;
    #pragma unroll
    for (int i = 0; i < 32; i++) { float2 f = unpack2(dd[i]); mx = fmaxf(mx, fmaxf(f.x, f.y)); }
    float off = diag + mx;
    #pragma unroll
    for (int i = 0; i < 16; i++) {
        float2 a = unpack2(dd[2*i]), c2 = unpack2(dd[2*i+1]);
        float4 o;
        o.x = RATIO*(__expf(a.x  - off) + EPSRF);
        o.y = RATIO*(__expf(a.y  - off) + EPSRF);
        o.z = RATIO*(__expf(c2.x - off) + EPSRF);
        o.w = RATIO*(__expf(c2.y - off) + EPSRF);
        *(float4*)&g_phiq[base + 4*i] = o;
    }

    // ---- keys ----
    sq = 0.f;
    #pragma unroll
    for (int c = 0; c < DD; c++) { float v = SFAC*(g_A2[n*DD+c] + c2s[c]); nv[c] = v; sq += v*v; }
    diag = 0.5f*sq;
    #pragma unroll
    for (int i = 0; i < 32; i++) dd[i] = 0ull;
    #pragma unroll 4
    for (int c = 0; c < DD; c++) {
        ull s = splat2(nv[c]);
        const ulonglong2* pp = (const ulonglong2*)&psT[c*MM];
        #pragma unroll
        for (int i = 0; i < 16; i++) {
            ulonglong2 pv = pp[i];
            fma2(dd[2*i],   s, pv.x);
            fma2(dd[2*i+1], s, pv.y);
        }
    }
    off = diag + g_stabk[b];
    #pragma unroll
    for (int i = 0; i < 16; i++) {
        float2 a = unpack2(dd[2*i]), c2 = unpack2(dd[2*i+1]);
        float4 o;
        o.x = RATIO*(__expf(a.x  - off) + EPSRF);
        o.y = RATIO*(__expf(a.y  - off) + EPSRF);
        o.z = RATIO*(__expf(c2.x - off) + EPSRF);
        o.w = RATIO*(__expf(c2.y - off) + EPSRF);
        *(float4*)&g_phik[base + 4*i] = o;
    }
}

// ---------------- input embedding + h/skip assembly ----------------
__global__ void k_input(const float* __restrict__ x,
                        const float* __restrict__ input_w,
                        const float* __restrict__ node_emb)
{
    int b = blockIdx.y, t = threadIdx.x;
    __shared__ float wts[TT*DD];
    __shared__ float mk[DD], tv[DD], wv[DD];
    for (int i = t; i < TT*DD; i += 128) {
        int tt = i / DD, c = i % DD;
        wts[i] = input_w[c*(3*TT)+tt];
    }
    if (t < DD) { mk[t] = g_mark[b*DD+t]; tv[t] = g_tvv[b*DD+t]; wv[t] = g_wvv[b*DD+t]; }
    __syncthreads();
    int n = blockIdx.x*128 + t;
    if (n >= NN) return;
    float acc[DD];
    #pragma unroll
    for (int c = 0; c < DD; c++) acc[c] = mk[c];
    for (int tt = 0; tt < TT; tt++) {
        float xv = x[((size_t)b*TT + tt)*NN + n];
        #pragma unroll
        for (int c = 0; c < DD; c++) acc[c] += xv * wts[tt*DD+c];
    }
    size_t base = ((size_t)(b*NN) + n) * CC;
    #pragma unroll
    for (int i = 0; i < 8; i++) {
        float4 v = make_float4(acc[4*i], acc[4*i+1], acc[4*i+2], acc[4*i+3]);
        *(float4*)&g_h[base + 4*i] = v; *(float4*)&g_skip[base + 4*i] = v;
    }
    #pragma unroll
    for (int i = 0; i < 8; i++) {
        float4 v = *(const float4*)&node_emb[n*DD + 4*i];
        *(float4*)&g_h[base + DD + 4*i] = v; *(float4*)&g_skip[base + DD + 4*i] = v;
    }
    #pragma unroll
    for (int i = 0; i < 8; i++) {
        float4 v = make_float4(tv[4*i], tv[4*i+1], tv[4*i+2], tv[4*i+3]);
        *(float4*)&g_h[base + 2*DD + 4*i] = v; *(float4*)&g_skip[base + 2*DD + 4*i] = v;
    }
    #pragma unroll
    for (int i = 0; i < 8; i++) {
        float4 v = make_float4(wv[4*i], wv[4*i+1], wv[4*i+2], wv[4*i+3]);
        *(float4*)&g_h[base + 3*DD + 4*i] = v; *(float4*)&g_skip[base + 3*DD + 4*i] = v;
    }
}

// ---------------- ksum = sum_n phi_k (deterministic chunked) ----------------
__global__ void k_ksum()
{
    int ch = blockIdx.x, b = blockIdx.y, t = threadIdx.x; // 256 thr
    int m = t & 63, sub = t >> 6;
    int n0 = ch*CHSZ;
    float acc = 0.f;
    for (int n = n0 + sub; n < n0 + CHSZ; n += 4)
        acc += g_phik[((size_t)(b*NN) + n)*MM + m];
    __shared__ float red[256];
    red[t] = acc;
    __syncthreads();
    if (t < 64)
        g_kspart[(b*NCH+ch)*MM + m] = red[m] + red[64+m] + red[128+m] + red[192+m];
}

__global__ void k_ksumred()
{
    int b = blockIdx.x, m = threadIdx.x;   // 64 threads
    float s = 0.f;
    for (int ch = 0; ch < NCH; ch++) s += g_kspart[(b*NCH+ch)*MM + m];
    g_ksum[b*MM+m] = s;
}

__global__ void k_den()
{
    int b = blockIdx.y, t = threadIdx.x;
    __shared__ float ks[MM];
    if (t < MM) ks[t] = g_ksum[b*MM+t];
    __syncthreads();
    int n = blockIdx.x*128 + t;
    if (n >= NN) return;
    size_t base = ((size_t)(b*NN) + n)*MM;
    float d = 0.f;
    #pragma unroll
    for (int m = 0; m < MM; m++) d += g_phiq[base+m]*ks[m];
    g_den[b*NN+n] = d;
}

// ---------------- gating GEMMs: u = sigmoid(h@Wi^T+bi) * (h@Wo^T+bo) --------
// 128x128 tile, 512 threads, per-thread 8r x 4c x 2 mats, f32x2 FMA.
__global__ __launch_bounds__(512) void k_gate(const float* __restrict__ in_w,
                                              const float* __restrict__ in_b,
                                              const float* __restrict__ out_w,
                                              const float* __restrict__ out_b,
                                              int layer)
{
    __shared__ float hs[32*128];
    __shared__ float wi[32*128];
    __shared__ float wo[32*128];
    int t = threadIdx.x;
    int cg = t & 31;        // cols cg*4..+3
    int rg = t >> 5;        // rows rg*8..+7 (0..15)
    size_t rowBase = (size_t)blockIdx.x * 128;
    const float* IW = in_w  + (size_t)layer*CC*CC;
    const float* OW = out_w + (size_t)layer*CC*CC;

    ull ai[4][4], ao[4][4];         // [row-pair][col]
    #pragma unroll
    for (int rp = 0; rp < 4; rp++)
        #pragma unroll
        for (int q = 0; q < 4; q++) { ai[rp][q] = 0ull; ao[rp][q] = 0ull; }

    for (int kc = 0; kc < 4; kc++) {
        #pragma unroll
        for (int L = 0; L < 2; L++) {
            int lin = t*2 + L;                // 0..1023
            int row = lin >> 3, q = lin & 7;  // row 0..127, q 0..7
            int ko = kc*32 + q*4;
            float4 hv  = *(const float4*)&g_h[(rowBase+row)*CC + ko];
            float4 wiv = *(const float4*)&IW[(size_t)row*CC + ko];
            float4 wov = *(const float4*)&OW[(size_t)row*CC + ko];
            hs[(q*4+0)*128+row]=hv.x;  hs[(q*4+1)*128+row]=hv.y;
            hs[(q*4+2)*128+row]=hv.z;  hs[(q*4+3)*128+row]=hv.w;
            wi[(q*4+0)*128+row]=wiv.x; wi[(q*4+1)*128+row]=wiv.y;
            wi[(q*4+2)*128+row]=wiv.z; wi[(q*4+3)*128+row]=wiv.w;
            wo[(q*4+0)*128+row]=wov.x; wo[(q*4+1)*128+row]=wov.y;
            wo[(q*4+2)*128+row]=wov.z; wo[(q*4+3)*128+row]=wov.w;
        }
        __syncthreads();
        #pragma unroll
        for (int j = 0; j < 32; j++) {
            ulonglong2 ra = *(const ulonglong2*)&hs[j*128 + rg*8];      // rows 0-1,2-3
            ulonglong2 rb = *(const ulonglong2*)&hs[j*128 + rg*8 + 4];  // rows 4-5,6-7
            float4 vi = *(const float4*)&wi[j*128 + cg*4];
            float4 vo = *(const float4*)&wo[j*128 + cg*4];
            ull rr[4] = {ra.x, ra.y, rb.x, rb.y};
            ull si[4] = {splat2(vi.x), splat2(vi.y), splat2(vi.z), splat2(vi.w)};
            ull so[4] = {splat2(vo.x), splat2(vo.y), splat2(vo.z), splat2(vo.w)};
            #pragma unroll
            for (int rp = 0; rp < 4; rp++)
                #pragma unroll
                for (int q = 0; q < 4; q++) {
                    fma2(ai[rp][q], rr[rp], si[q]);
                    fma2(ao[rp][q], rr[rp], so[q]);
                }
        }
        __syncthreads();
    }
    float bi[4], bo[4];
    #pragma unroll
    for (int q = 0; q < 4; q++) {
        bi[q] = in_b [layer*CC + cg*4 + q];
        bo[q] = out_b[layer*CC + cg*4 + q];
    }
    #pragma unroll
    for (int rp = 0; rp < 4; rp++) {
        float2 i0 = unpack2(ai[rp][0]), i1 = unpack2(ai[rp][1]),
               i2 = unpack2(ai[rp][2]), i3 = unpack2(ai[rp][3]);
        float2 o0 = unpack2(ao[rp][0]), o1 = unpack2(ao[rp][1]),
               o2 = unpack2(ao[rp][2]), o3 = unpack2(ao[rp][3]);
        size_t r0 = rowBase + rg*8 + 2*rp;
        float4 uv;
        uv.x = (o0.x+bo[0]) / (1.0f+__expf(-(i0.x+bi[0])));
        uv.y = (o1.x+bo[1]) / (1.0f+__expf(-(i1.x+bi[1])));
        uv.z = (o2.x+bo[2]) / (1.0f+__expf(-(i2.x+bi[2])));
        uv.w = (o3.x+bo[3]) / (1.0f+__expf(-(i3.x+bi[3])));
        *(float4*)&g_u[r0*CC + cg*4] = uv;
        uv.x = (o0.y+bo[0]) / (1.0f+__expf(-(i0.y+bi[0])));
        uv.y = (o1.y+bo[1]) / (1.0f+__expf(-(i1.y+bi[1])));
        uv.z = (o2.y+bo[2]) / (1.0f+__expf(-(i2.y+bi[2])));
        uv.w = (o3.y+bo[3]) / (1.0f+__expf(-(i3.y+bi[3])));
        *(float4*)&g_u[(r0+1)*CC + cg*4] = uv;
    }
}

// ---------------- kv partials: kv[m][c] = sum_n phik[n][m] * u[n][c] --------
__global__ __launch_bounds__(128) void k_kv()
{
    int ch = blockIdx.x, b = blockIdx.y, t = threadIdx.x;  // 128 threads
    __shared__ float phs[4*64];
    __shared__ float us[4*128];
    int mb = (t & 7)*8, cb = (t >> 3)*8;
    ull acc[8][4];                    // [m-row][col-pair]
    #pragma unroll
    for (int i = 0; i < 8; i++)
        #pragma unroll
        for (int j = 0; j < 4; j++) acc[i][j] = 0ull;
    int n0 = ch*CHSZ;
    for (int it = 0; it < CHSZ/4; it++) {
        int nb = n0 + it*4;
        __syncthreads();
        #pragma unroll
        for (int k = 0; k < 6; k++) {
            int lin = t + k*128;
            if (lin < 256) {
                int nn = lin >> 6, m = lin & 63;
                phs[nn*64+m] = g_phik[((size_t)(b*NN) + nb + nn)*MM + m];
            } else {
                int l2 = lin - 256;
                int nn = l2 >> 7, c = l2 & 127;
                us[nn*128+c] = g_u[((size_t)(b*NN) + nb + nn)*CC + c];
            }
        }
        __syncthreads();
        #pragma unroll
        for (int nn = 0; nn < 4; nn++) {
            float4 p0 = *(const float4*)&phs[nn*64+mb];
            float4 p1 = *(const float4*)&phs[nn*64+mb+4];
            ulonglong2 u0 = *(const ulonglong2*)&us[nn*128+cb];
            ulonglong2 u1 = *(const ulonglong2*)&us[nn*128+cb+4];
            ull up[4] = {u0.x, u0.y, u1.x, u1.y};
            float pm[8] = {p0.x,p0.y,p0.z,p0.w,p1.x,p1.y,p1.z,p1.w};
            #pragma unroll
            for (int i = 0; i < 8; i++) {
                ull ps_ = splat2(pm[i]);
                #pragma unroll
                for (int j = 0; j < 4; j++) fma2(acc[i][j], ps_, up[j]);
            }
        }
    }
    float* dst = &g_kvpart[((size_t)(b*NCH) + ch)*MM*CC];
    #pragma unroll
    for (int i = 0; i < 8; i++)
        #pragma unroll
        for (int j = 0; j < 4; j++)
            *(ull*)&dst[(mb+i)*CC + cb + 2*j] = acc[i][j];
}

__global__ void k_kvred()
{
    int b = blockIdx.y, t = threadIdx.x;       // grid (32, BB), 256 thr
    int i = blockIdx.x*256 + t;                // 8192 elems
    float s = 0.f;
    for (int ch = 0; ch < NCH; ch++)
        s += g_kvpart[((size_t)(b*NCH) + ch)*MM*CC + i];
    g_kv[b*MM*CC + i] = s;
}

// ---------------- num GEMM + divide + residual + LN (fused, f32x2) ---------
// [128 rows x 64 m] @ [64 m x 128 c], 256 threads, 8x8 micro-tile.
#define SMEM_NUM ((8192 + 8320) * 4)
__global__ __launch_bounds__(256) void k_num(const float* __restrict__ ln_g,
                                             const float* __restrict__ ln_b,
                                             int layer)
{
    extern __shared__ float sm[];
    float* kvs = sm;               // 64*128 = 8192
    float* pqs = sm + 8192;        // phiq tile [row][m] stride 65 (8320); reused as stage
    int b = blockIdx.y, t = threadIdx.x;
    int nbase = blockIdx.x*128;

    for (int i = t; i < MM*CC; i += 256) kvs[i] = g_kv[b*MM*CC + i];
    for (int i = t; i < 128*16; i += 256) {
        int row = i >> 4, m4 = (i & 15)*4;
        int n = nbase + row;
        float4 v = make_float4(0.f,0.f,0.f,0.f);
        if (n < NN) v = *(const float4*)&g_phiq[((size_t)(b*NN)+n)*MM + m4];
        pqs[row*65+m4]   = v.x; pqs[row*65+m4+1] = v.y;
        pqs[row*65+m4+2] = v.z; pqs[row*65+m4+3] = v.w;
    }
    __syncthreads();

    int rg = t >> 4, cg = t & 15;          // rows rg*8..+7, cols cg*8..+7
    ull acc[8][4];
    #pragma unroll
    for (int r = 0; r < 8; r++)
        #pragma unroll
        for (int q = 0; q < 4; q++) acc[r][q] = 0ull;
    const float* pr = &pqs[rg*8*65];
    for (int m = 0; m < MM; m++) {
        ulonglong2 u0 = *(const ulonglong2*)&kvs[m*CC + cg*8];
        ulonglong2 u1 = *(const ulonglong2*)&kvs[m*CC + cg*8 + 4];
        ull bp[4] = {u0.x, u0.y, u1.x, u1.y};
        #pragma unroll
        for (int r = 0; r < 8; r++) {
            ull as = splat2(pr[r*65 + m]);
            #pragma unroll
            for (int q = 0; q < 4; q++) fma2(acc[r][q], as, bp[q]);
        }
    }

    // epilogue: two 64-row halves staged into pqs (reused as stage stride 128)
    float* stage = pqs;
    int w = t >> 5, lane = t & 31;
    for (int half = 0; half < 2; half++) {
        __syncthreads();
        if ((rg >> 3) == half) {
            int r0 = (rg & 7)*8;
            #pragma unroll
            for (int r = 0; r < 8; r++)
                #pragma unroll
                for (int q = 0; q < 4; q++)
                    *(ull*)&stage[(r0+r)*128 + cg*8 + 2*q] = acc[r][q];
        }
        __syncthreads();
        #pragma unroll
        for (int rr = 0; rr < 8; rr++) {
            int lrow = w*8 + rr;                       // 0..63
            int n = nbase + half*64 + lrow;
            float4 nv4 = *(const float4*)&stage[lrow*128 + lane*4];
            float4 h4 = make_float4(0.f,0.f,0.f,0.f);
            float den = 1.f;
            size_t idx = ((size_t)(b*NN) + n)*CC + lane*4;
            if (n < NN) { h4 = *(const float4*)&g_h[idx]; den = g_den[b*NN+n]; }
            float r_ = 1.0f / den;
            float v0 = nv4.x*r_ + h4.x, v1 = nv4.y*r_ + h4.y;
            float v2 = nv4.z*r_ + h4.z, v3 = nv4.w*r_ + h4.w;
            float s  = v0+v1+v2+v3;
            float s2 = v0*v0+v1*v1+v2*v2+v3*v3;
            #pragma unroll
            for (int o = 16; o; o >>= 1) {
                s  += __shfl_xor_sync(0xffffffffu, s,  o);
                s2 += __shfl_xor_sync(0xffffffffu, s2, o);
            }
            float mu  = s * (1.0f/128.0f);
            float var = s2 * (1.0f/128.0f) - mu*mu;
            float is  = rsqrtf(var + 1e-5f);
            if (n < NN) {
                float4 g4 = *(const float4*)&ln_g[layer*CC + lane*4];
                float4 b4 = *(const float4*)&ln_b[layer*CC + lane*4];
                float4 o4;
                o4.x = (v0-mu)*is*g4.x + b4.x;
                o4.y = (v1-mu)*is*g4.y + b4.y;
                o4.z = (v2-mu)*is*g4.z + b4.z;
                o4.w = (v3-mu)*is*g4.w + b4.w;
                *(float4*)&g_h[idx] = o4;
            }
        }
    }
}

// ---------------- regression head ----------------
__global__ void k_reg(const float* __restrict__ reg_w,
                      const float* __restrict__ reg_b,
                      float* __restrict__ out)
{
    int b = blockIdx.y, t = threadIdx.x;   // 128 threads, t = local node
    __shared__ float rw[PP*2*CC];          // 12 KB
    __shared__ float st[128*33];           // padded transpose tile
    for (int i = t; i < PP*2*CC; i += 128) rw[i] = reg_w[i];
    int nbase = blockIdx.x*128;
    float acc[PP];
    #pragma unroll
    for (int p = 0; p < PP; p++) acc[p] = 0.f;
    for (int src = 0; src < 2; src++) {
        const float* S = src ? g_h : g_skip;
        for (int c0 = 0; c0 < CC; c0 += 32) {
            __syncthreads();
            #pragma unroll
            for (int k = 0; k < 32; k++) {
                int lin = t + k*128;
                int rr = lin >> 5, cc = lin & 31;
                int n = nbase + rr;
                st[rr*33+cc] = (n < NN) ? S[((size_t)(b*NN) + n)*CC + c0 + cc] : 0.f;
            }
            __syncthreads();
            #pragma unroll
            for (int cc = 0; cc < 32; cc++) {
                float v = st[t*33+cc];
                #pragma unroll
                for (int p = 0; p < PP; p++)
                    acc[p] += v * rw[p*(2*CC) + src*CC + c0 + cc];
            }
        }
    }
    int n = nbase + t;
    if (n < NN) {
        #pragma unroll
        for (int p = 0; p < PP; p++)
            out[((size_t)(b*PP) + p)*NN + n] = acc[p] + reg_b[p];
    }
}

// ---------------- launcher ----------------
extern "C" void kernel_launch(void* const* d_in, const int* in_sizes, int n_in,
                              void* d_out, int out_size)
{
    const float* x        = (const float*)d_in[0];
    const float* xmark    = (const float*)d_in[1];
    const float* node_emb = (const float*)d_in[2];
    const float* time_tab = (const float*)d_in[3];
    const float* week_tab = (const float*)d_in[4];
    const float* input_w  = (const float*)d_in[5];
    const float* input_b  = (const float*)d_in[6];
    const float* w1_w     = (const float*)d_in[7];
    const float* w1_b     = (const float*)d_in[8];
    const float* w2_w     = (const float*)d_in[9];
    const float* w2_b     = (const float*)d_in[10];
    const float* in_w     = (const float*)d_in[11];
    const float* in_b     = (const float*)d_in[12];
    const float* out_w    = (const float*)d_in[13];
    const float* out_b    = (const float*)d_in[14];
    const float* ln_g     = (const float*)d_in[15];
    const float* ln_b     = (const float*)d_in[16];
    const float* reg_w    = (const float*)d_in[17];
    const float* reg_b    = (const float*)d_in[18];
    const float* proj     = (const float*)d_in[19];
    float* out = (float*)d_out;

    cudaFuncSetAttribute(k_num, cudaFuncAttributeMaxDynamicSharedMemorySize, SMEM_NUM);

    dim3 gBN((NN + 127)/128, BB);

    k_const<<<BB, 128>>>(xmark, time_tab, week_tab, input_w, input_b,
                         w1_w, w1_b, w2_w, w2_b, proj);
    k_node<<<(NN + 255)/256, 256>>>(node_emb, w1_w, w2_w);
    k_colmax<<<MM, 256>>>(proj);
    k_stab<<<BB, 64>>>();
    k_phi<<<gBN, 128>>>(proj);
    k_input<<<gBN, 128>>>(x, input_w, node_emb);
    k_ksum<<<dim3(NCH, BB), 256>>>();
    k_ksumred<<<BB, 64>>>();
    k_den<<<gBN, 128>>>();

    for (int l = 0; l < LL; l++) {
        k_gate<<<RTOT/128, 512>>>(in_w, in_b, out_w, out_b, l);
        k_kv<<<dim3(NCH, BB), 128>>>();
        k_kvred<<<dim3(32, BB), 256>>>();
        k_num<<<gBN, 256, SMEM_NUM>>>(ln_g, ln_b, l);
    }
    k_reg<<<gBN, 128>>>(reg_w, reg_b, out);
}

// round 8
// speedup vs baseline: 1.4926x; 1.0690x over previous
#include <cuda_runtime.h>
#include <math.h>

// Problem constants
#define BB 8
#define TT 96
#define NN 20000
#define PP 12
#define LL 3
#define DD 32
#define CC 128
#define MM 64
#define NBLK 157              // ceil(NN/128) row-blocks per batch
#define NCH 100               // node chunks for ksum partials
#define CHSZ (NN/NCH)         // 200

#define SFAC 0.4204482076268573f   // 32^{-1/4}
#define RATIO 0.125f               // 1/sqrt(64)
#define EPSRF 1e-6f

typedef unsigned long long ull;

// ---- packed fp32x2 helpers (SASS FFMA2 — only reachable via PTX) ----
__device__ __forceinline__ ull splat2(float v){
    ull r; asm("mov.b64 %0, {%1, %1};" : "=l"(r) : "f"(v)); return r;
}
__device__ __forceinline__ void fma2(ull& acc, ull a, ull b){
    asm("fma.rn.f32x2 %0, %1, %2, %0;" : "+l"(acc) : "l"(a), "l"(b));
}
__device__ __forceinline__ float2 unpack2(ull v){
    float2 f; asm("mov.b64 {%0, %1}, %2;" : "=f"(f.x), "=f"(f.y) : "l"(v)); return f;
}

// ---------------- device scratch (static globals: allocation-free) ----------
__device__ float g_h   [(size_t)BB*NN*CC];
__device__ float g_skip[(size_t)BB*NN*CC];
__device__ float g_phiq[(size_t)BB*NN*MM];
__device__ float g_phik[(size_t)BB*NN*MM];
__device__ float g_A1[NN*DD];
__device__ float g_A2[NN*DD];
__device__ float g_c1[BB*DD];
__device__ float g_c2[BB*DD];
__device__ float g_Pc2[BB*MM];
__device__ float g_mark[BB*DD];
__device__ float g_tvv[BB*DD];
__device__ float g_wvv[BB*DD];
__device__ float g_colmax[MM];
__device__ float g_stabk[BB];
__device__ float g_kvpart[(size_t)BB*NBLK*MM*CC];
__device__ float g_kv[BB*MM*CC];
__device__ float g_kspart[BB*NCH*MM];
__device__ float g_ksum[BB*MM];
__device__ float g_den[BB*NN];

// ---------------- per-batch constants -----------------
__global__ void k_const(const float* __restrict__ xmark,
                        const float* __restrict__ time_tab,
                        const float* __restrict__ week_tab,
                        const float* __restrict__ input_w,
                        const float* __restrict__ input_b,
                        const float* __restrict__ w1_w, const float* __restrict__ w1_b,
                        const float* __restrict__ w2_w, const float* __restrict__ w2_b,
                        const float* __restrict__ proj)
{
    int b = blockIdx.x, t = threadIdx.x;
    __shared__ float xm0[TT], xm1[TT], stv[DD], swv[DD], sc1[DD], sc2[DD];

    float m0 = xmark[(b*TT + (TT-1))*2 + 0];
    float m1 = xmark[(b*TT + (TT-1))*2 + 1];
    int tod = (int)(m0 * (float)TT); tod = min(max(tod, 0), TT-1);
    int dow = (int)(m1 * 7.0f);      dow = min(max(dow, 0), 6);

    if (t < TT) { xm0[t] = xmark[(b*TT+t)*2]; xm1[t] = xmark[(b*TT+t)*2+1]; }
    if (t < DD) {
        float tv = time_tab[tod*DD+t], wv = week_tab[dow*DD+t];
        stv[t] = tv; swv[t] = wv;
        g_tvv[b*DD+t] = tv; g_wvv[b*DD+t] = wv;
    }
    __syncthreads();
    if (t < DD) {
        float mc = input_b[t];
        for (int k = 0; k < TT; k++)
            mc += xm0[k]*input_w[t*(3*TT)+TT+k] + xm1[k]*input_w[t*(3*TT)+2*TT+k];
        g_mark[b*DD+t] = mc;
        float v1 = w1_b[t], v2 = w2_b[t];
        for (int g = 0; g < DD; g++) {
            v1 += stv[g]*w1_w[t*(3*DD)+DD+g] + swv[g]*w1_w[t*(3*DD)+2*DD+g];
            v2 += stv[g]*w2_w[t*(3*DD)+DD+g] + swv[g]*w2_w[t*(3*DD)+2*DD+g];
        }
        v1 *= 2.0f; v2 *= 2.0f;                  // 1/sqrt(tau) = 2
        sc1[t] = v1; sc2[t] = v2;
        g_c1[b*DD+t] = v1; g_c2[b*DD+t] = v2;
    }
    __syncthreads();
    if (t < MM) {
        float p = 0.f;
        #pragma unroll
        for (int c = 0; c < DD; c++) p += sc2[c]*proj[t*DD+c];
        g_Pc2[b*MM+t] = SFAC * p;
    }
}

// ---------------- node-dependent parts of nv1/nv2 ----------------
__global__ void k_node(const float* __restrict__ node_emb,
                       const float* __restrict__ w1_w,
                       const float* __restrict__ w2_w)
{
    __shared__ float w1s[DD*DD], w2s[DD*DD];
    int t = threadIdx.x;
    for (int i = t; i < DD*DD; i += 256) {
        int c = i / DD, g = i % DD;
        w1s[i] = w1_w[c*(3*DD)+g];
        w2s[i] = w2_w[c*(3*DD)+g];
    }
    __syncthreads();
    int n = blockIdx.x*256 + t;
    if (n >= NN) return;
    float ne[DD];
    #pragma unroll
    for (int g = 0; g < DD; g++) ne[g] = node_emb[n*DD+g];
    #pragma unroll 4
    for (int c = 0; c < DD; c++) {
        float a1 = 0.f, a2 = 0.f;
        #pragma unroll
        for (int g = 0; g < DD; g++) { a1 += ne[g]*w1s[c*DD+g]; a2 += ne[g]*w2s[c*DD+g]; }
        g_A1[n*DD+c] = 2.0f*a1;
        g_A2[n*DD+c] = 2.0f*a2;
    }
}

// ---------------- per-feature max over nodes of s * A2 . proj[m] -----------
__global__ void k_colmax(const float* __restrict__ proj)
{
    int m = blockIdx.x, t = threadIdx.x;
    __shared__ float pr[DD];
    __shared__ float red[8];
    if (t < DD) pr[t] = proj[m*DD+t];
    __syncthreads();
    float mx = -1e30f;
    for (int n = t; n < NN; n += 256) {
        float d = 0.f;
        #pragma unroll
        for (int c = 0; c < DD; c++) d += g_A2[n*DD+c]*pr[c];
        mx = fmaxf(mx, d);
    }
    for (int o = 16; o; o >>= 1) mx = fmaxf(mx, __shfl_down_sync(0xffffffffu, mx, o));
    if ((t & 31) == 0) red[t >> 5] = mx;
    __syncthreads();
    if (t == 0) {
        float r = red[0];
        for (int w = 1; w < 8; w++) r = fmaxf(r, red[w]);
        g_colmax[m] = SFAC * r;
    }
}

__global__ void k_stab()
{
    int b = blockIdx.x, t = threadIdx.x;     // 64 threads
    __shared__ float red[2];
    float v = g_colmax[t] + g_Pc2[b*MM+t];
    for (int o = 16; o; o >>= 1) v = fmaxf(v, __shfl_down_sync(0xffffffffu, v, o));
    if ((t & 31) == 0) red[t >> 5] = v;
    __syncthreads();
    if (t == 0) g_stabk[b] = fmaxf(red[0], red[1]);
}

// ---------------- FAVOR+ random features (dash in regs, f32x2, __expf) -----
__global__ __launch_bounds__(128) void k_phi(const float* __restrict__ proj)
{
    int b = blockIdx.y, t = threadIdx.x;
    __shared__ float psT[DD*MM];              // transposed: [c][m]
    __shared__ float c1s[DD], c2s[DD];
    for (int i = t; i < DD*MM; i += 128) {
        int m = i >> 5, c = i & 31;
        psT[c*MM+m] = proj[m*DD+c];
    }
    if (t < DD) { c1s[t] = g_c1[b*DD+t]; c2s[t] = g_c2[b*DD+t]; }
    __syncthreads();
    int n = blockIdx.x*128 + t;
    if (n >= NN) return;

    size_t base = ((size_t)(b*NN) + n) * MM;
    ull dd[32];
    float nv[DD];

    // ---- queries ----
    float sq = 0.f;
    #pragma unroll
    for (int c = 0; c < DD; c++) { float v = SFAC*(g_A1[n*DD+c] + c1s[c]); nv[c] = v; sq += v*v; }
    float diag = 0.5f*sq;
    #pragma unroll
    for (int i = 0; i < 32; i++) dd[i] = 0ull;
    #pragma unroll 4
    for (int c = 0; c < DD; c++) {
        ull s = splat2(nv[c]);
        const ulonglong2* pp = (const ulonglong2*)&psT[c*MM];
        #pragma unroll
        for (int i = 0; i < 16; i++) {
            ulonglong2 pv = pp[i];
            fma2(dd[2*i],   s, pv.x);
            fma2(dd[2*i+1], s, pv.y);
        }
    }
    float mx = -1e30f;
    #pragma unroll
    for (int i = 0; i < 32; i++) { float2 f = unpack2(dd[i]); mx = fmaxf(mx, fmaxf(f.x, f.y)); }
    float off = diag + mx;
    #pragma unroll
    for (int i = 0; i < 16; i++) {
        float2 a = unpack2(dd[2*i]), c2 = unpack2(dd[2*i+1]);
        float4 o;
        o.x = RATIO*(__expf(a.x  - off) + EPSRF);
        o.y = RATIO*(__expf(a.y  - off) + EPSRF);
        o.z = RATIO*(__expf(c2.x - off) + EPSRF);
        o.w = RATIO*(__expf(c2.y - off) + EPSRF);
        *(float4*)&g_phiq[base + 4*i] = o;
    }

    // ---- keys ----
    sq = 0.f;
    #pragma unroll
    for (int c = 0; c < DD; c++) { float v = SFAC*(g_A2[n*DD+c] + c2s[c]); nv[c] = v; sq += v*v; }
    diag = 0.5f*sq;
    #pragma unroll
    for (int i = 0; i < 32; i++) dd[i] = 0ull;
    #pragma unroll 4
    for (int c = 0; c < DD; c++) {
        ull s = splat2(nv[c]);
        const ulonglong2* pp = (const ulonglong2*)&psT[c*MM];
        #pragma unroll
        for (int i = 0; i < 16; i++) {
            ulonglong2 pv = pp[i];
            fma2(dd[2*i],   s, pv.x);
            fma2(dd[2*i+1], s, pv.y);
        }
    }
    off = diag + g_stabk[b];
    #pragma unroll
    for (int i = 0; i < 16; i++) {
        float2 a = unpack2(dd[2*i]), c2 = unpack2(dd[2*i+1]);
        float4 o;
        o.x = RATIO*(__expf(a.x  - off) + EPSRF);
        o.y = RATIO*(__expf(a.y  - off) + EPSRF);
        o.z = RATIO*(__expf(c2.x - off) + EPSRF);
        o.w = RATIO*(__expf(c2.y - off) + EPSRF);
        *(float4*)&g_phik[base + 4*i] = o;
    }
}

// ---------------- input embedding + h/skip assembly ----------------
__global__ void k_input(const float* __restrict__ x,
                        const float* __restrict__ input_w,
                        const float* __restrict__ node_emb)
{
    int b = blockIdx.y, t = threadIdx.x;
    __shared__ float wts[TT*DD];
    __shared__ float mk[DD], tv[DD], wv[DD];
    for (int i = t; i < TT*DD; i += 128) {
        int tt = i / DD, c = i % DD;
        wts[i] = input_w[c*(3*TT)+tt];
    }
    if (t < DD) { mk[t] = g_mark[b*DD+t]; tv[t] = g_tvv[b*DD+t]; wv[t] = g_wvv[b*DD+t]; }
    __syncthreads();
    int n = blockIdx.x*128 + t;
    if (n >= NN) return;
    float acc[DD];
    #pragma unroll
    for (int c = 0; c < DD; c++) acc[c] = mk[c];
    for (int tt = 0; tt < TT; tt++) {
        float xv = x[((size_t)b*TT + tt)*NN + n];
        #pragma unroll
        for (int c = 0; c < DD; c++) acc[c] += xv * wts[tt*DD+c];
    }
    size_t base = ((size_t)(b*NN) + n) * CC;
    #pragma unroll
    for (int i = 0; i < 8; i++) {
        float4 v = make_float4(acc[4*i], acc[4*i+1], acc[4*i+2], acc[4*i+3]);
        *(float4*)&g_h[base + 4*i] = v; *(float4*)&g_skip[base + 4*i] = v;
    }
    #pragma unroll
    for (int i = 0; i < 8; i++) {
        float4 v = *(const float4*)&node_emb[n*DD + 4*i];
        *(float4*)&g_h[base + DD + 4*i] = v; *(float4*)&g_skip[base + DD + 4*i] = v;
    }
    #pragma unroll
    for (int i = 0; i < 8; i++) {
        float4 v = make_float4(tv[4*i], tv[4*i+1], tv[4*i+2], tv[4*i+3]);
        *(float4*)&g_h[base + 2*DD + 4*i] = v; *(float4*)&g_skip[base + 2*DD + 4*i] = v;
    }
    #pragma unroll
    for (int i = 0; i < 8; i++) {
        float4 v = make_float4(wv[4*i], wv[4*i+1], wv[4*i+2], wv[4*i+3]);
        *(float4*)&g_h[base + 3*DD + 4*i] = v; *(float4*)&g_skip[base + 3*DD + 4*i] = v;
    }
}

// ---------------- ksum = sum_n phi_k (deterministic chunked) ----------------
__global__ void k_ksum()
{
    int ch = blockIdx.x, b = blockIdx.y, t = threadIdx.x; // 256 thr
    int m = t & 63, sub = t >> 6;
    int n0 = ch*CHSZ;
    float acc = 0.f;
    for (int n = n0 + sub; n < n0 + CHSZ; n += 4)
        acc += g_phik[((size_t)(b*NN) + n)*MM + m];
    __shared__ float red[256];
    red[t] = acc;
    __syncthreads();
    if (t < 64)
        g_kspart[(b*NCH+ch)*MM + m] = red[m] + red[64+m] + red[128+m] + red[192+m];
}

__global__ void k_ksumred()
{
    int b = blockIdx.x, m = threadIdx.x;   // 64 threads
    float s = 0.f;
    for (int ch = 0; ch < NCH; ch++) s += g_kspart[(b*NCH+ch)*MM + m];
    g_ksum[b*MM+m] = s;
}

__global__ void k_den()
{
    int b = blockIdx.y, t = threadIdx.x;
    __shared__ float ks[MM];
    if (t < MM) ks[t] = g_ksum[b*MM+t];
    __syncthreads();
    int n = blockIdx.x*128 + t;
    if (n >= NN) return;
    size_t base = ((size_t)(b*NN) + n)*MM;
    float d = 0.f;
    #pragma unroll
    for (int m = 0; m < MM; m++) d += g_phiq[base+m]*ks[m];
    g_den[b*NN+n] = d;
}

// ---------------- fused gate + kv-partial -----------------------------------
// Per block: 128 rows of one batch. Computes u = sigmoid(h@Wi^T+bi)*(h@Wo^T+bo)
// into an SMEM tile (never gmem), then kv_part[m][c] = sum_rows phik[r][m]*u[r][c].
// Dynamic smem: u tile 64 KB (region A) + 48 KB stage (region B, reused for phik).
#define SMEM_GATE ((16384 + 12288) * 4)
__global__ __launch_bounds__(512) void k_gatekv(const float* __restrict__ in_w,
                                                const float* __restrict__ in_b,
                                                const float* __restrict__ out_w,
                                                const float* __restrict__ out_b,
                                                int layer)
{
    extern __shared__ float sm[];
    float* us = sm;                 // 128 x 128 u tile (16384 floats)
    float* hs = sm + 16384;         // stage region B: 3 x 4096 floats
    float* wi = sm + 16384 + 4096;
    float* wo = sm + 16384 + 8192;
    float* pk = sm + 16384;         // phik tile 128 x 64, reuses region B

    int t = threadIdx.x;
    int blk = blockIdx.x, b = blockIdx.y;
    int cg = t & 31;        // cols cg*4..+3
    int rg = t >> 5;        // rows rg*8..+7 (0..15)
    int n0 = blk*128;
    size_t batchBase = (size_t)b*NN;
    const float* IW = in_w  + (size_t)layer*CC*CC;
    const float* OW = out_w + (size_t)layer*CC*CC;

    ull ai[4][4], ao[4][4];         // [row-pair][col]
    #pragma unroll
    for (int rp = 0; rp < 4; rp++)
        #pragma unroll
        for (int q = 0; q < 4; q++) { ai[rp][q] = 0ull; ao[rp][q] = 0ull; }

    for (int kc = 0; kc < 4; kc++) {
        #pragma unroll
        for (int L = 0; L < 2; L++) {
            int lin = t*2 + L;                // 0..1023
            int row = lin >> 3, q = lin & 7;  // row 0..127, q 0..7
            int ko = kc*32 + q*4;
            int nrow = min(n0 + row, NN-1);   // clamp (finite values; guards via phik=0)
            float4 hv  = *(const float4*)&g_h[(batchBase + nrow)*CC + ko];
            float4 wiv = *(const float4*)&IW[(size_t)row*CC + ko];
            float4 wov = *(const float4*)&OW[(size_t)row*CC + ko];
            hs[(q*4+0)*128+row]=hv.x;  hs[(q*4+1)*128+row]=hv.y;
            hs[(q*4+2)*128+row]=hv.z;  hs[(q*4+3)*128+row]=hv.w;
            wi[(q*4+0)*128+row]=wiv.x; wi[(q*4+1)*128+row]=wiv.y;
            wi[(q*4+2)*128+row]=wiv.z; wi[(q*4+3)*128+row]=wiv.w;
            wo[(q*4+0)*128+row]=wov.x; wo[(q*4+1)*128+row]=wov.y;
            wo[(q*4+2)*128+row]=wov.z; wo[(q*4+3)*128+row]=wov.w;
        }
        __syncthreads();
        #pragma unroll
        for (int j = 0; j < 32; j++) {
            ulonglong2 ra = *(const ulonglong2*)&hs[j*128 + rg*8];
            ulonglong2 rb = *(const ulonglong2*)&hs[j*128 + rg*8 + 4];
            float4 vi = *(const float4*)&wi[j*128 + cg*4];
            float4 vo = *(const float4*)&wo[j*128 + cg*4];
            ull rr[4] = {ra.x, ra.y, rb.x, rb.y};
            ull si[4] = {splat2(vi.x), splat2(vi.y), splat2(vi.z), splat2(vi.w)};
            ull so[4] = {splat2(vo.x), splat2(vo.y), splat2(vo.z), splat2(vo.w)};
            #pragma unroll
            for (int rp = 0; rp < 4; rp++)
                #pragma unroll
                for (int q = 0; q < 4; q++) {
                    fma2(ai[rp][q], rr[rp], si[q]);
                    fma2(ao[rp][q], rr[rp], so[q]);
                }
        }
        __syncthreads();
    }

    // epilogue → u tile in SMEM (zero guard rows so kv partial stays exact)
    float bi[4], bo[4];
    #pragma unroll
    for (int q = 0; q < 4; q++) {
        bi[q] = in_b [layer*CC + cg*4 + q];
        bo[q] = out_b[layer*CC + cg*4 + q];
    }
    #pragma unroll
    for (int rp = 0; rp < 4; rp++) {
        float2 i0 = unpack2(ai[rp][0]), i1 = unpack2(ai[rp][1]),
               i2 = unpack2(ai[rp][2]), i3 = unpack2(ai[rp][3]);
        float2 o0 = unpack2(ao[rp][0]), o1 = unpack2(ao[rp][1]),
               o2 = unpack2(ao[rp][2]), o3 = unpack2(ao[rp][3]);
        int r0 = rg*8 + 2*rp;
        float4 uv;
        bool v0ok = (n0 + r0)     < NN;
        bool v1ok = (n0 + r0 + 1) < NN;
        uv.x = v0ok ? (o0.x+bo[0]) / (1.0f+__expf(-(i0.x+bi[0]))) : 0.f;
        uv.y = v0ok ? (o1.x+bo[1]) / (1.0f+__expf(-(i1.x+bi[1]))) : 0.f;
        uv.z = v0ok ? (o2.x+bo[2]) / (1.0f+__expf(-(i2.x+bi[2]))) : 0.f;
        uv.w = v0ok ? (o3.x+bo[3]) / (1.0f+__expf(-(i3.x+bi[3]))) : 0.f;
        *(float4*)&us[r0*128 + cg*4] = uv;
        uv.x = v1ok ? (o0.y+bo[0]) / (1.0f+__expf(-(i0.y+bi[0]))) : 0.f;
        uv.y = v1ok ? (o1.y+bo[1]) / (1.0f+__expf(-(i1.y+bi[1]))) : 0.f;
        uv.z = v1ok ? (o2.y+bo[2]) / (1.0f+__expf(-(i2.y+bi[2]))) : 0.f;
        uv.w = v1ok ? (o3.y+bo[3]) / (1.0f+__expf(-(i3.y+bi[3]))) : 0.f;
        *(float4*)&us[(r0+1)*128 + cg*4] = uv;
    }

    // phik tile → region B (rows beyond NN get 0)
    #pragma unroll
    for (int k = 0; k < 4; k++) {
        int lin = t + k*512;                  // 0..2047
        int row = lin >> 4, m4 = (lin & 15)*4;
        int n = n0 + row;
        float4 v = make_float4(0.f,0.f,0.f,0.f);
        if (n < NN) v = *(const float4*)&g_phik[(batchBase + n)*MM + m4];
        *(float4*)&pk[row*64 + m4] = v;
    }
    __syncthreads();

    // kv partial: [64 m x 128 c] = pk^T @ us ; thread -> 4m x 4c
    int mg = t >> 5;          // 0..15 -> m = mg*4..+3
    int ck = t & 31;          // c = ck*4..+3
    ull acc[4][2];
    #pragma unroll
    for (int i = 0; i < 4; i++) { acc[i][0] = 0ull; acc[i][1] = 0ull; }
    #pragma unroll 4
    for (int row = 0; row < 128; row++) {
        float4 pm = *(const float4*)&pk[row*64 + mg*4];
        ulonglong2 uc = *(const ulonglong2*)&us[row*128 + ck*4];
        ull s0 = splat2(pm.x), s1 = splat2(pm.y), s2 = splat2(pm.z), s3 = splat2(pm.w);
        fma2(acc[0][0], s0, uc.x); fma2(acc[0][1], s0, uc.y);
        fma2(acc[1][0], s1, uc.x); fma2(acc[1][1], s1, uc.y);
        fma2(acc[2][0], s2, uc.x); fma2(acc[2][1], s2, uc.y);
        fma2(acc[3][0], s3, uc.x); fma2(acc[3][1], s3, uc.y);
    }
    float* dst = &g_kvpart[((size_t)(b*NBLK) + blk)*MM*CC];
    #pragma unroll
    for (int i = 0; i < 4; i++) {
        *(ull*)&dst[(mg*4+i)*CC + ck*4]     = acc[i][0];
        *(ull*)&dst[(mg*4+i)*CC + ck*4 + 2] = acc[i][1];
    }
}

__global__ void k_kvred()
{
    int b = blockIdx.y, t = threadIdx.x;       // grid (32, BB), 256 thr
    int i = blockIdx.x*256 + t;                // 8192 elems
    float s = 0.f;
    for (int blk = 0; blk < NBLK; blk++)
        s += g_kvpart[((size_t)(b*NBLK) + blk)*MM*CC + i];
    g_kv[b*MM*CC + i] = s;
}

// ---------------- num GEMM + divide + residual + LN (fused, f32x2) ---------
// [128 rows x 64 m] @ [64 m x 128 c], 256 threads, 8x8 micro-tile.
#define SMEM_NUM ((8192 + 8320) * 4)
__global__ __launch_bounds__(256) void k_num(const float* __restrict__ ln_g,
                                             const float* __restrict__ ln_b,
                                             int layer)
{
    extern __shared__ float sm[];
    float* kvs = sm;               // 64*128 = 8192
    float* pqs = sm + 8192;        // phiq tile [row][m] stride 65 (8320); reused as stage
    int b = blockIdx.y, t = threadIdx.x;
    int nbase = blockIdx.x*128;

    for (int i = t; i < MM*CC; i += 256) kvs[i] = g_kv[b*MM*CC + i];
    for (int i = t; i < 128*16; i += 256) {
        int row = i >> 4, m4 = (i & 15)*4;
        int n = nbase + row;
        float4 v = make_float4(0.f,0.f,0.f,0.f);
        if (n < NN) v = *(const float4*)&g_phiq[((size_t)(b*NN)+n)*MM + m4];
        pqs[row*65+m4]   = v.x; pqs[row*65+m4+1] = v.y;
        pqs[row*65+m4+2] = v.z; pqs[row*65+m4+3] = v.w;
    }
    __syncthreads();

    int rg = t >> 4, cg = t & 15;          // rows rg*8..+7, cols cg*8..+7
    ull acc[8][4];
    #pragma unroll
    for (int r = 0; r < 8; r++)
        #pragma unroll
        for (int q = 0; q < 4; q++) acc[r][q] = 0ull;
    const float* pr = &pqs[rg*8*65];
    for (int m = 0; m < MM; m++) {
        ulonglong2 u0 = *(const ulonglong2*)&kvs[m*CC + cg*8];
        ulonglong2 u1 = *(const ulonglong2*)&kvs[m*CC + cg*8 + 4];
        ull bp[4] = {u0.x, u0.y, u1.x, u1.y};
        #pragma unroll
        for (int r = 0; r < 8; r++) {
            ull as = splat2(pr[r*65 + m]);
            #pragma unroll
            for (int q = 0; q < 4; q++) fma2(acc[r][q], as, bp[q]);
        }
    }

    // epilogue: two 64-row halves staged into pqs (reused as stage stride 128)
    float* stage = pqs;
    int w = t >> 5, lane = t & 31;
    for (int half = 0; half < 2; half++) {
        __syncthreads();
        if ((rg >> 3) == half) {
            int r0 = (rg & 7)*8;
            #pragma unroll
            for (int r = 0; r < 8; r++)
                #pragma unroll
                for (int q = 0; q < 4; q++)
                    *(ull*)&stage[(r0+r)*128 + cg*8 + 2*q] = acc[r][q];
        }
        __syncthreads();
        #pragma unroll
        for (int rr = 0; rr < 8; rr++) {
            int lrow = w*8 + rr;                       // 0..63
            int n = nbase + half*64 + lrow;
            float4 nv4 = *(const float4*)&stage[lrow*128 + lane*4];
            float4 h4 = make_float4(0.f,0.f,0.f,0.f);
            float den = 1.f;
            size_t idx = ((size_t)(b*NN) + n)*CC + lane*4;
            if (n < NN) { h4 = *(const float4*)&g_h[idx]; den = g_den[b*NN+n]; }
            float r_ = 1.0f / den;
            float v0 = nv4.x*r_ + h4.x, v1 = nv4.y*r_ + h4.y;
            float v2 = nv4.z*r_ + h4.z, v3 = nv4.w*r_ + h4.w;
            float s  = v0+v1+v2+v3;
            float s2 = v0*v0+v1*v1+v2*v2+v3*v3;
            #pragma unroll
            for (int o = 16; o; o >>= 1) {
                s  += __shfl_xor_sync(0xffffffffu, s,  o);
                s2 += __shfl_xor_sync(0xffffffffu, s2, o);
            }
            float mu  = s * (1.0f/128.0f);
            float var = s2 * (1.0f/128.0f) - mu*mu;
            float is  = rsqrtf(var + 1e-5f);
            if (n < NN) {
                float4 g4 = *(const float4*)&ln_g[layer*CC + lane*4];
                float4 b4 = *(const float4*)&ln_b[layer*CC + lane*4];
                float4 o4;
                o4.x = (v0-mu)*is*g4.x + b4.x;
                o4.y = (v1-mu)*is*g4.y + b4.y;
                o4.z = (v2-mu)*is*g4.z + b4.z;
                o4.w = (v3-mu)*is*g4.w + b4.w;
                *(float4*)&g_h[idx] = o4;
            }
        }
    }
}

// ---------------- regression head ----------------
__global__ void k_reg(const float* __restrict__ reg_w,
                      const float* __restrict__ reg_b,
                      float* __restrict__ out)
{
    int b = blockIdx.y, t = threadIdx.x;   // 128 threads, t = local node
    __shared__ float rw[PP*2*CC];          // 12 KB
    __shared__ float st[128*33];           // padded transpose tile
    for (int i = t; i < PP*2*CC; i += 128) rw[i] = reg_w[i];
    int nbase = blockIdx.x*128;
    float acc[PP];
    #pragma unroll
    for (int p = 0; p < PP; p++) acc[p] = 0.f;
    for (int src = 0; src < 2; src++) {
        const float* S = src ? g_h : g_skip;
        for (int c0 = 0; c0 < CC; c0 += 32) {
            __syncthreads();
            #pragma unroll
            for (int k = 0; k < 32; k++) {
                int lin = t + k*128;
                int rr = lin >> 5, cc = lin & 31;
                int n = nbase + rr;
                st[rr*33+cc] = (n < NN) ? S[((size_t)(b*NN) + n)*CC + c0 + cc] : 0.f;
            }
            __syncthreads();
            #pragma unroll
            for (int cc = 0; cc < 32; cc++) {
                float v = st[t*33+cc];
                #pragma unroll
                for (int p = 0; p < PP; p++)
                    acc[p] += v * rw[p*(2*CC) + src*CC + c0 + cc];
            }
        }
    }
    int n = nbase + t;
    if (n < NN) {
        #pragma unroll
        for (int p = 0; p < PP; p++)
            out[((size_t)(b*PP) + p)*NN + n] = acc[p] + reg_b[p];
    }
}

// ---------------- launcher ----------------
extern "C" void kernel_launch(void* const* d_in, const int* in_sizes, int n_in,
                              void* d_out, int out_size)
{
    const float* x        = (const float*)d_in[0];
    const float* xmark    = (const float*)d_in[1];
    const float* node_emb = (const float*)d_in[2];
    const float* time_tab = (const float*)d_in[3];
    const float* week_tab = (const float*)d_in[4];
    const float* input_w  = (const float*)d_in[5];
    const float* input_b  = (const float*)d_in[6];
    const float* w1_w     = (const float*)d_in[7];
    const float* w1_b     = (const float*)d_in[8];
    const float* w2_w     = (const float*)d_in[9];
    const float* w2_b     = (const float*)d_in[10];
    const float* in_w     = (const float*)d_in[11];
    const float* in_b     = (const float*)d_in[12];
    const float* out_w    = (const float*)d_in[13];
    const float* out_b    = (const float*)d_in[14];
    const float* ln_g     = (const float*)d_in[15];
    const float* ln_b     = (const float*)d_in[16];
    const float* reg_w    = (const float*)d_in[17];
    const float* reg_b    = (const float*)d_in[18];
    const float* proj     = (const float*)d_in[19];
    float* out = (float*)d_out;

    cudaFuncSetAttribute(k_num,    cudaFuncAttributeMaxDynamicSharedMemorySize, SMEM_NUM);
    cudaFuncSetAttribute(k_gatekv, cudaFuncAttributeMaxDynamicSharedMemorySize, SMEM_GATE);

    dim3 gBN(NBLK, BB);

    k_const<<<BB, 128>>>(xmark, time_tab, week_tab, input_w, input_b,
                         w1_w, w1_b, w2_w, w2_b, proj);
    k_node<<<(NN + 255)/256, 256>>>(node_emb, w1_w, w2_w);
    k_colmax<<<MM, 256>>>(proj);
    k_stab<<<BB, 64>>>();
    k_phi<<<gBN, 128>>>(proj);
    k_input<<<gBN, 128>>>(x, input_w, node_emb);
    k_ksum<<<dim3(NCH, BB), 256>>>();
    k_ksumred<<<BB, 64>>>();
    k_den<<<gBN, 128>>>();

    for (int l = 0; l < LL; l++) {
        k_gatekv<<<gBN, 512, SMEM_GATE>>>(in_w, in_b, out_w, out_b, l);
        k_kvred<<<dim3(32, BB), 256>>>();
        k_num<<<gBN, 256, SMEM_NUM>>>(ln_g, ln_b, l);
    }
    k_reg<<<gBN, 128>>>(reg_w, reg_b, out);
}

// round 12
// speedup vs baseline: 1.7180x; 1.1510x over previous
#include <cuda_runtime.h>
#include <cuda_bf16.h>
#include <math.h>
#include <stdint.h>

// Problem constants
#define BB 8
#define TT 96
#define NN 20000
#define PP 12
#define LL 3
#define DD 32
#define CC 128
#define MM 64
#define NBLK 157              // ceil(NN/128) row-blocks per batch
#define NCH 100               // node chunks for ksum partials
#define CHSZ (NN/NCH)         // 200

#define SFAC 0.4204482076268573f   // 32^{-1/4}
#define RATIO 0.125f               // 1/sqrt(64)
#define EPSRF 1e-6f

typedef unsigned long long ull;

// ---- packed fp32x2 helpers ----
__device__ __forceinline__ ull splat2(float v){
    ull r; asm("mov.b64 %0, {%1, %1};" : "=l"(r) : "f"(v)); return r;
}
__device__ __forceinline__ void fma2(ull& acc, ull a, ull b){
    asm("fma.rn.f32x2 %0, %1, %2, %0;" : "+l"(acc) : "l"(a), "l"(b));
}
__device__ __forceinline__ float2 unpack2(ull v){
    float2 f; asm("mov.b64 {%0, %1}, %2;" : "=f"(f.x), "=f"(f.y) : "l"(v)); return f;
}

// ---- HMMA helper: base-ISA bf16 mma (compiles for compute_103) ----
__device__ __forceinline__ void mma_bf16(float d[4], const uint32_t a[4], const uint32_t b[2]){
    asm volatile("mma.sync.aligned.m16n8k16.row.col.f32.bf16.bf16.f32 "
        "{%0,%1,%2,%3}, {%4,%5,%6,%7}, {%8,%9}, {%0,%1,%2,%3};"
        : "+f"(d[0]), "+f"(d[1]), "+f"(d[2]), "+f"(d[3])
        : "r"(a[0]), "r"(a[1]), "r"(a[2]), "r"(a[3]), "r"(b[0]), "r"(b[1]));
}
__device__ __forceinline__ uint32_t packbf(float a, float b){
    __nv_bfloat162 h = __floats2bfloat162_rn(a, b);
    uint32_t r; memcpy(&r, &h, 4); return r;
}
__device__ __forceinline__ uint32_t lds_u32(const char* base, int elem){   // elem in bf16 units
    return *(const uint32_t*)(base + elem*2);
}

// ---------------- device scratch ----------
__device__ float g_h   [(size_t)BB*NN*CC];
__device__ float g_skip[(size_t)BB*NN*CC];
__device__ float g_phiq[(size_t)BB*NN*MM];
__device__ float g_phik[(size_t)BB*NN*MM];
__device__ float g_A1[NN*DD];
__device__ float g_A2[NN*DD];
__device__ float g_c1[BB*DD];
__device__ float g_c2[BB*DD];
__device__ float g_Pc2[BB*MM];
__device__ float g_mark[BB*DD];
__device__ float g_tvv[BB*DD];
__device__ float g_wvv[BB*DD];
__device__ float g_colmax[MM];
__device__ float g_stabk[BB];
__device__ float g_kvpart[(size_t)BB*NBLK*MM*CC];
__device__ float g_kv[BB*MM*CC];
__device__ float g_kspart[BB*NCH*MM];
__device__ float g_ksum[BB*MM];
__device__ float g_den[BB*NN];

// ---------------- per-batch constants -----------------
__global__ void k_const(const float* __restrict__ xmark,
                        const float* __restrict__ time_tab,
                        const float* __restrict__ week_tab,
                        const float* __restrict__ input_w,
                        const float* __restrict__ input_b,
                        const float* __restrict__ w1_w, const float* __restrict__ w1_b,
                        const float* __restrict__ w2_w, const float* __restrict__ w2_b,
                        const float* __restrict__ proj)
{
    int b = blockIdx.x, t = threadIdx.x;
    __shared__ float xm0[TT], xm1[TT], stv[DD], swv[DD], sc1[DD], sc2[DD];

    float m0 = xmark[(b*TT + (TT-1))*2 + 0];
    float m1 = xmark[(b*TT + (TT-1))*2 + 1];
    int tod = (int)(m0 * (float)TT); tod = min(max(tod, 0), TT-1);
    int dow = (int)(m1 * 7.0f);      dow = min(max(dow, 0), 6);

    if (t < TT) { xm0[t] = xmark[(b*TT+t)*2]; xm1[t] = xmark[(b*TT+t)*2+1]; }
    if (t < DD) {
        float tv = time_tab[tod*DD+t], wv = week_tab[dow*DD+t];
        stv[t] = tv; swv[t] = wv;
        g_tvv[b*DD+t] = tv; g_wvv[b*DD+t] = wv;
    }
    __syncthreads();
    if (t < DD) {
        float mc = input_b[t];
        for (int k = 0; k < TT; k++)
            mc += xm0[k]*input_w[t*(3*TT)+TT+k] + xm1[k]*input_w[t*(3*TT)+2*TT+k];
        g_mark[b*DD+t] = mc;
        float v1 = w1_b[t], v2 = w2_b[t];
        for (int g = 0; g < DD; g++) {
            v1 += stv[g]*w1_w[t*(3*DD)+DD+g] + swv[g]*w1_w[t*(3*DD)+2*DD+g];
            v2 += stv[g]*w2_w[t*(3*DD)+DD+g] + swv[g]*w2_w[t*(3*DD)+2*DD+g];
        }
        v1 *= 2.0f; v2 *= 2.0f;
        sc1[t] = v1; sc2[t] = v2;
        g_c1[b*DD+t] = v1; g_c2[b*DD+t] = v2;
    }
    __syncthreads();
    if (t < MM) {
        float p = 0.f;
        #pragma unroll
        for (int c = 0; c < DD; c++) p += sc2[c]*proj[t*DD+c];
        g_Pc2[b*MM+t] = SFAC * p;
    }
}

__global__ void k_node(const float* __restrict__ node_emb,
                       const float* __restrict__ w1_w,
                       const float* __restrict__ w2_w)
{
    __shared__ float w1s[DD*DD], w2s[DD*DD];
    int t = threadIdx.x;
    for (int i = t; i < DD*DD; i += 256) {
        int c = i / DD, g = i % DD;
        w1s[i] = w1_w[c*(3*DD)+g];
        w2s[i] = w2_w[c*(3*DD)+g];
    }
    __syncthreads();
    int n = blockIdx.x*256 + t;
    if (n >= NN) return;
    float ne[DD];
    #pragma unroll
    for (int g = 0; g < DD; g++) ne[g] = node_emb[n*DD+g];
    #pragma unroll 4
    for (int c = 0; c < DD; c++) {
        float a1 = 0.f, a2 = 0.f;
        #pragma unroll
        for (int g = 0; g < DD; g++) { a1 += ne[g]*w1s[c*DD+g]; a2 += ne[g]*w2s[c*DD+g]; }
        g_A1[n*DD+c] = 2.0f*a1;
        g_A2[n*DD+c] = 2.0f*a2;
    }
}

__global__ void k_colmax(const float* __restrict__ proj)
{
    int m = blockIdx.x, t = threadIdx.x;
    __shared__ float pr[DD];
    __shared__ float red[8];
    if (t < DD) pr[t] = proj[m*DD+t];
    __syncthreads();
    float mx = -1e30f;
    for (int n = t; n < NN; n += 256) {
        float d = 0.f;
        #pragma unroll
        for (int c = 0; c < DD; c++) d += g_A2[n*DD+c]*pr[c];
        mx = fmaxf(mx, d);
    }
    for (int o = 16; o; o >>= 1) mx = fmaxf(mx, __shfl_down_sync(0xffffffffu, mx, o));
    if ((t & 31) == 0) red[t >> 5] = mx;
    __syncthreads();
    if (t == 0) {
        float r = red[0];
        for (int w = 1; w < 8; w++) r = fmaxf(r, red[w]);
        g_colmax[m] = SFAC * r;
    }
}

__global__ void k_stab()
{
    int b = blockIdx.x, t = threadIdx.x;
    __shared__ float red[2];
    float v = g_colmax[t] + g_Pc2[b*MM+t];
    for (int o = 16; o; o >>= 1) v = fmaxf(v, __shfl_down_sync(0xffffffffu, v, o));
    if ((t & 31) == 0) red[t >> 5] = v;
    __syncthreads();
    if (t == 0) g_stabk[b] = fmaxf(red[0], red[1]);
}

__global__ __launch_bounds__(128) void k_phi(const float* __restrict__ proj)
{
    int b = blockIdx.y, t = threadIdx.x;
    __shared__ float psT[DD*MM];
    __shared__ float c1s[DD], c2s[DD];
    for (int i = t; i < DD*MM; i += 128) {
        int m = i >> 5, c = i & 31;
        psT[c*MM+m] = proj[m*DD+c];
    }
    if (t < DD) { c1s[t] = g_c1[b*DD+t]; c2s[t] = g_c2[b*DD+t]; }
    __syncthreads();
    int n = blockIdx.x*128 + t;
    if (n >= NN) return;

    size_t base = ((size_t)(b*NN) + n) * MM;
    ull dd[32];
    float nv[DD];

    float sq = 0.f;
    #pragma unroll
    for (int c = 0; c < DD; c++) { float v = SFAC*(g_A1[n*DD+c] + c1s[c]); nv[c] = v; sq += v*v; }
    float diag = 0.5f*sq;
    #pragma unroll
    for (int i = 0; i < 32; i++) dd[i] = 0ull;
    #pragma unroll 4
    for (int c = 0; c < DD; c++) {
        ull s = splat2(nv[c]);
        const ulonglong2* pp = (const ulonglong2*)&psT[c*MM];
        #pragma unroll
        for (int i = 0; i < 16; i++) {
            ulonglong2 pv = pp[i];
            fma2(dd[2*i],   s, pv.x);
            fma2(dd[2*i+1], s, pv.y);
        }
    }
    float mx = -1e30f;
    #pragma unroll
    for (int i = 0; i < 32; i++) { float2 f = unpack2(dd[i]); mx = fmaxf(mx, fmaxf(f.x, f.y)); }
    float off = diag + mx;
    #pragma unroll
    for (int i = 0; i < 16; i++) {
        float2 a = unpack2(dd[2*i]), c2 = unpack2(dd[2*i+1]);
        float4 o;
        o.x = RATIO*(__expf(a.x  - off) + EPSRF);
        o.y = RATIO*(__expf(a.y  - off) + EPSRF);
        o.z = RATIO*(__expf(c2.x - off) + EPSRF);
        o.w = RATIO*(__expf(c2.y - off) + EPSRF);
        *(float4*)&g_phiq[base + 4*i] = o;
    }

    sq = 0.f;
    #pragma unroll
    for (int c = 0; c < DD; c++) { float v = SFAC*(g_A2[n*DD+c] + c2s[c]); nv[c] = v; sq += v*v; }
    diag = 0.5f*sq;
    #pragma unroll
    for (int i = 0; i < 32; i++) dd[i] = 0ull;
    #pragma unroll 4
    for (int c = 0; c < DD; c++) {
        ull s = splat2(nv[c]);
        const ulonglong2* pp = (const ulonglong2*)&psT[c*MM];
        #pragma unroll
        for (int i = 0; i < 16; i++) {
            ulonglong2 pv = pp[i];
            fma2(dd[2*i],   s, pv.x);
            fma2(dd[2*i+1], s, pv.y);
        }
    }
    off = diag + g_stabk[b];
    #pragma unroll
    for (int i = 0; i < 16; i++) {
        float2 a = unpack2(dd[2*i]), c2 = unpack2(dd[2*i+1]);
        float4 o;
        o.x = RATIO*(__expf(a.x  - off) + EPSRF);
        o.y = RATIO*(__expf(a.y  - off) + EPSRF);
        o.z = RATIO*(__expf(c2.x - off) + EPSRF);
        o.w = RATIO*(__expf(c2.y - off) + EPSRF);
        *(float4*)&g_phik[base + 4*i] = o;
    }
}

__global__ void k_input(const float* __restrict__ x,
                        const float* __restrict__ input_w,
                        const float* __restrict__ node_emb)
{
    int b = blockIdx.y, t = threadIdx.x;
    __shared__ float wts[TT*DD];
    __shared__ float mk[DD], tv[DD], wv[DD];
    for (int i = t; i < TT*DD; i += 128) {
        int tt = i / DD, c = i % DD;
        wts[i] = input_w[c*(3*TT)+tt];
    }
    if (t < DD) { mk[t] = g_mark[b*DD+t]; tv[t] = g_tvv[b*DD+t]; wv[t] = g_wvv[b*DD+t]; }
    __syncthreads();
    int n = blockIdx.x*128 + t;
    if (n >= NN) return;
    float acc[DD];
    #pragma unroll
    for (int c = 0; c < DD; c++) acc[c] = mk[c];
    for (int tt = 0; tt < TT; tt++) {
        float xv = x[((size_t)b*TT + tt)*NN + n];
        #pragma unroll
        for (int c = 0; c < DD; c++) acc[c] += xv * wts[tt*DD+c];
    }
    size_t base = ((size_t)(b*NN) + n) * CC;
    #pragma unroll
    for (int i = 0; i < 8; i++) {
        float4 v = make_float4(acc[4*i], acc[4*i+1], acc[4*i+2], acc[4*i+3]);
        *(float4*)&g_h[base + 4*i] = v; *(float4*)&g_skip[base + 4*i] = v;
    }
    #pragma unroll
    for (int i = 0; i < 8; i++) {
        float4 v = *(const float4*)&node_emb[n*DD + 4*i];
        *(float4*)&g_h[base + DD + 4*i] = v; *(float4*)&g_skip[base + DD + 4*i] = v;
    }
    #pragma unroll
    for (int i = 0; i < 8; i++) {
        float4 v = make_float4(tv[4*i], tv[4*i+1], tv[4*i+2], tv[4*i+3]);
        *(float4*)&g_h[base + 2*DD + 4*i] = v; *(float4*)&g_skip[base + 2*DD + 4*i] = v;
    }
    #pragma unroll
    for (int i = 0; i < 8; i++) {
        float4 v = make_float4(wv[4*i], wv[4*i+1], wv[4*i+2], wv[4*i+3]);
        *(float4*)&g_h[base + 3*DD + 4*i] = v; *(float4*)&g_skip[base + 3*DD + 4*i] = v;
    }
}

__global__ void k_ksum()
{
    int ch = blockIdx.x, b = blockIdx.y, t = threadIdx.x;
    int m = t & 63, sub = t >> 6;
    int n0 = ch*CHSZ;
    float acc = 0.f;
    for (int n = n0 + sub; n < n0 + CHSZ; n += 4)
        acc += g_phik[((size_t)(b*NN) + n)*MM + m];
    __shared__ float red[256];
    red[t] = acc;
    __syncthreads();
    if (t < 64)
        g_kspart[(b*NCH+ch)*MM + m] = red[m] + red[64+m] + red[128+m] + red[192+m];
}

__global__ void k_ksumred()
{
    int b = blockIdx.x, m = threadIdx.x;
    float s = 0.f;
    for (int ch = 0; ch < NCH; ch++) s += g_kspart[(b*NCH+ch)*MM + m];
    g_ksum[b*MM+m] = s;
}

__global__ void k_den()
{
    int b = blockIdx.y, t = threadIdx.x;
    __shared__ float ks[MM];
    if (t < MM) ks[t] = g_ksum[b*MM+t];
    __syncthreads();
    int n = blockIdx.x*128 + t;
    if (n >= NN) return;
    size_t base = ((size_t)(b*NN) + n)*MM;
    float d = 0.f;
    #pragma unroll
    for (int m = 0; m < MM; m++) d += g_phiq[base+m]*ks[m];
    g_den[b*NN+n] = d;
}

// ---------------- fused gate (bf16-split HMMA) + kv-partial ------------------
// Dynamic smem: 6 bf16 tiles [128 x 136] (Ah, Al, Ih, Il, Oh, Ol); the fp32
// U tile (stride 132) reuses Ah+Al after MMA; PK reuses Ih.
#define STR   136                       // bf16 elems per row
#define TSZ   (128*STR*2)               // 34816 B per tile
#define SMEM_GATE (6*TSZ)               // 208896 B
#define USTRIDE 132

__device__ __forceinline__ void split_store(char* hiP, char* loP, float4 a, float4 c){
    float av[8] = {a.x,a.y,a.z,a.w,c.x,c.y,c.z,c.w};
    float l[8];
    #pragma unroll
    for (int j = 0; j < 8; j++) {
        float hb = __bfloat162float(__float2bfloat16(av[j]));
        l[j] = av[j] - hb;
    }
    uint4 hi, lo;
    hi.x = packbf(av[0],av[1]); hi.y = packbf(av[2],av[3]);
    hi.z = packbf(av[4],av[5]); hi.w = packbf(av[6],av[7]);
    lo.x = packbf(l[0],l[1]);   lo.y = packbf(l[2],l[3]);
    lo.z = packbf(l[4],l[5]);   lo.w = packbf(l[6],l[7]);
    *(uint4*)hiP = hi;
    *(uint4*)loP = lo;
}

__global__ __launch_bounds__(512)
void k_gatekv(const float* __restrict__ in_w,
              const float* __restrict__ in_b,
              const float* __restrict__ out_w,
              const float* __restrict__ out_b,
              int layer)
{
    extern __shared__ __align__(16) char smem[];
    char* AH = smem;
    char* AL = smem + TSZ;
    char* IH = smem + 2*TSZ;
    char* IL = smem + 3*TSZ;
    char* OH = smem + 4*TSZ;
    char* OL = smem + 5*TSZ;

    int t = threadIdx.x;
    int wid = t >> 5, lid = t & 31;
    int lane4 = lid >> 2, lanem = lid & 3;
    int blk = blockIdx.x, b = blockIdx.y;
    int n0 = blk*128;
    size_t batchBase = (size_t)b*NN;
    const float* IW = in_w  + (size_t)layer*CC*CC;
    const float* OW = out_w + (size_t)layer*CC*CC;

    // ---- convert h, Wi, Wo to bf16 hi/lo tiles ----
    #pragma unroll
    for (int it = 0; it < 4; it++) {
        int lin = t + it*512;                // 0..2047
        int row = lin >> 4, seg = lin & 15;
        int c8 = seg*8;
        int boff = row*(STR*2) + c8*2;
        int nrow = min(n0 + row, NN-1);
        float4 a = *(const float4*)&g_h[(batchBase + nrow)*CC + c8];
        float4 c = *(const float4*)&g_h[(batchBase + nrow)*CC + c8 + 4];
        split_store(AH + boff, AL + boff, a, c);
        a = *(const float4*)&IW[(size_t)row*CC + c8];
        c = *(const float4*)&IW[(size_t)row*CC + c8 + 4];
        split_store(IH + boff, IL + boff, a, c);
        a = *(const float4*)&OW[(size_t)row*CC + c8];
        c = *(const float4*)&OW[(size_t)row*CC + c8 + 4];
        split_store(OH + boff, OL + boff, a, c);
    }
    __syncthreads();

    // ---- warp tiling: 16 warps, each owns a 32x32 output tile ----
    int mrow = (wid & 3)*32;
    int ncol = (wid >> 2)*32;

    float di[2][4][4], dq[2][4][4];
    #pragma unroll
    for (int mt = 0; mt < 2; mt++)
        #pragma unroll
        for (int nt = 0; nt < 4; nt++)
            #pragma unroll
            for (int j = 0; j < 4; j++) { di[mt][nt][j] = 0.f; dq[mt][nt][j] = 0.f; }

    // pass 1: A_hi x (B_hi and B_lo)
    #pragma unroll
    for (int kk = 0; kk < 8; kk++) {
        int k0 = kk*16;
        uint32_t a[2][4];
        #pragma unroll
        for (int mt = 0; mt < 2; mt++) {
            int r = mrow + mt*16 + lane4;
            int cidx = k0 + lanem*2;
            a[mt][0] = lds_u32(AH, r*STR + cidx);
            a[mt][1] = lds_u32(AH, (r+8)*STR + cidx);
            a[mt][2] = lds_u32(AH, r*STR + cidx + 8);
            a[mt][3] = lds_u32(AH, (r+8)*STR + cidx + 8);
        }
        #pragma unroll
        for (int nt = 0; nt < 4; nt++) {
            int nr = ncol + nt*8 + lane4;
            int koff = k0 + lanem*2;
            uint32_t bih[2] = { lds_u32(IH, nr*STR + koff), lds_u32(IH, nr*STR + koff + 8) };
            uint32_t boh[2] = { lds_u32(OH, nr*STR + koff), lds_u32(OH, nr*STR + koff + 8) };
            uint32_t bil[2] = { lds_u32(IL, nr*STR + koff), lds_u32(IL, nr*STR + koff + 8) };
            uint32_t bol[2] = { lds_u32(OL, nr*STR + koff), lds_u32(OL, nr*STR + koff + 8) };
            mma_bf16(di[0][nt], a[0], bih); mma_bf16(di[1][nt], a[1], bih);
            mma_bf16(dq[0][nt], a[0], boh); mma_bf16(dq[1][nt], a[1], boh);
            mma_bf16(di[0][nt], a[0], bil); mma_bf16(di[1][nt], a[1], bil);
            mma_bf16(dq[0][nt], a[0], bol); mma_bf16(dq[1][nt], a[1], bol);
        }
    }
    // pass 2: A_lo x B_hi
    #pragma unroll
    for (int kk = 0; kk < 8; kk++) {
        int k0 = kk*16;
        uint32_t a[2][4];
        #pragma unroll
        for (int mt = 0; mt < 2; mt++) {
            int r = mrow + mt*16 + lane4;
            int cidx = k0 + lanem*2;
            a[mt][0] = lds_u32(AL, r*STR + cidx);
            a[mt][1] = lds_u32(AL, (r+8)*STR + cidx);
            a[mt][2] = lds_u32(AL, r*STR + cidx + 8);
            a[mt][3] = lds_u32(AL, (r+8)*STR + cidx + 8);
        }
        #pragma unroll
        for (int nt = 0; nt < 4; nt++) {
            int nr = ncol + nt*8 + lane4;
            int koff = k0 + lanem*2;
            uint32_t bih[2] = { lds_u32(IH, nr*STR + koff), lds_u32(IH, nr*STR + koff + 8) };
            uint32_t boh[2] = { lds_u32(OH, nr*STR + koff), lds_u32(OH, nr*STR + koff + 8) };
            mma_bf16(di[0][nt], a[0], bih); mma_bf16(di[1][nt], a[1], bih);
            mma_bf16(dq[0][nt], a[0], boh); mma_bf16(dq[1][nt], a[1], boh);
        }
    }
    __syncthreads();   // all tile reads done; safe to overwrite with U / PK

    // ---- epilogue: u = (Do+bo)*sigmoid(Di+bi) from D fragments -> U tile ----
    float* U  = (float*)smem;            // 128 x USTRIDE fp32 (reuses AH+AL)
    float* PK = (float*)(smem + 2*TSZ);  // 128 x 64 fp32 (reuses IH)
    #pragma unroll
    for (int mt = 0; mt < 2; mt++) {
        #pragma unroll
        for (int half = 0; half < 2; half++) {
            int row = mrow + mt*16 + lane4 + half*8;
            bool ok = (n0 + row) < NN;
            #pragma unroll
            for (int nt = 0; nt < 4; nt++) {
                int col = ncol + nt*8 + lanem*2;
                float2 bi2 = *(const float2*)&in_b [layer*CC + col];
                float2 bo2 = *(const float2*)&out_b[layer*CC + col];
                float v0 = di[mt][nt][half*2+0] + bi2.x;
                float v1 = di[mt][nt][half*2+1] + bi2.y;
                float2 uv;
                uv.x = ok ? (dq[mt][nt][half*2+0]+bo2.x) / (1.f+__expf(-v0)) : 0.f;
                uv.y = ok ? (dq[mt][nt][half*2+1]+bo2.y) / (1.f+__expf(-v1)) : 0.f;
                *(float2*)&U[row*USTRIDE + col] = uv;
            }
        }
    }
    // phik tile (rows beyond NN -> 0)
    #pragma unroll
    for (int it = 0; it < 4; it++) {
        int i = t + it*512;
        int row = i >> 4, m4 = (i & 15)*4;
        int n = n0 + row;
        float4 v = make_float4(0.f,0.f,0.f,0.f);
        if (n < NN) v = *(const float4*)&g_phik[(batchBase + n)*MM + m4];
        *(float4*)&PK[row*64 + m4] = v;
    }
    __syncthreads();

    // ---- kv partial: [64 m x 128 c] = PK^T @ U ; thread -> 4m x 4c --------
    {
        int mg = t >> 5;          // warp id -> m = mg*4..+3 (PK broadcast per warp)
        int ck = t & 31;          // c = ck*4..+3
        ull acc[4][2];
        #pragma unroll
        for (int i = 0; i < 4; i++) { acc[i][0] = 0ull; acc[i][1] = 0ull; }
        #pragma unroll 4
        for (int row = 0; row < 128; row++) {
            float4 pm = *(const float4*)&PK[row*64 + mg*4];
            ulonglong2 uc = *(const ulonglong2*)&U[row*USTRIDE + ck*4];
            ull s0 = splat2(pm.x), s1 = splat2(pm.y), s2 = splat2(pm.z), s3 = splat2(pm.w);
            fma2(acc[0][0], s0, uc.x); fma2(acc[0][1], s0, uc.y);
            fma2(acc[1][0], s1, uc.x); fma2(acc[1][1], s1, uc.y);
            fma2(acc[2][0], s2, uc.x); fma2(acc[2][1], s2, uc.y);
            fma2(acc[3][0], s3, uc.x); fma2(acc[3][1], s3, uc.y);
        }
        float* dst = &g_kvpart[((size_t)(b*NBLK) + blk)*MM*CC];
        #pragma unroll
        for (int i = 0; i < 4; i++) {
            *(ull*)&dst[(mg*4+i)*CC + ck*4]     = acc[i][0];
            *(ull*)&dst[(mg*4+i)*CC + ck*4 + 2] = acc[i][1];
        }
    }
}

__global__ void k_kvred()
{
    int b = blockIdx.y, t = threadIdx.x;       // grid (32, BB), 256 thr
    int i = blockIdx.x*256 + t;
    float s = 0.f;
    for (int blk = 0; blk < NBLK; blk++)
        s += g_kvpart[((size_t)(b*NBLK) + blk)*MM*CC + i];
    g_kv[b*MM*CC + i] = s;
}

// ---------------- num GEMM + divide + residual + LN (fused, f32x2) ---------
#define SMEM_NUM ((8192 + 8320) * 4)
__global__ __launch_bounds__(256) void k_num(const float* __restrict__ ln_g,
                                             const float* __restrict__ ln_b,
                                             int layer)
{
    extern __shared__ float sm[];
    float* kvs = sm;
    float* pqs = sm + 8192;
    int b = blockIdx.y, t = threadIdx.x;
    int nbase = blockIdx.x*128;

    for (int i = t; i < MM*CC; i += 256) kvs[i] = g_kv[b*MM*CC + i];
    for (int i = t; i < 128*16; i += 256) {
        int row = i >> 4, m4 = (i & 15)*4;
        int n = nbase + row;
        float4 v = make_float4(0.f,0.f,0.f,0.f);
        if (n < NN) v = *(const float4*)&g_phiq[((size_t)(b*NN)+n)*MM + m4];
        pqs[row*65+m4]   = v.x; pqs[row*65+m4+1] = v.y;
        pqs[row*65+m4+2] = v.z; pqs[row*65+m4+3] = v.w;
    }
    __syncthreads();

    int rg = t >> 4, cg = t & 15;
    ull acc[8][4];
    #pragma unroll
    for (int r = 0; r < 8; r++)
        #pragma unroll
        for (int q = 0; q < 4; q++) acc[r][q] = 0ull;
    const float* pr = &pqs[rg*8*65];
    for (int m = 0; m < MM; m++) {
        ulonglong2 u0 = *(const ulonglong2*)&kvs[m*CC + cg*8];
        ulonglong2 u1 = *(const ulonglong2*)&kvs[m*CC + cg*8 + 4];
        ull bp[4] = {u0.x, u0.y, u1.x, u1.y};
        #pragma unroll
        for (int r = 0; r < 8; r++) {
            ull as = splat2(pr[r*65 + m]);
            #pragma unroll
            for (int q = 0; q < 4; q++) fma2(acc[r][q], as, bp[q]);
        }
    }

    float* stage = pqs;
    int w = t >> 5, lane = t & 31;
    for (int half = 0; half < 2; half++) {
        __syncthreads();
        if ((rg >> 3) == half) {
            int r0 = (rg & 7)*8;
            #pragma unroll
            for (int r = 0; r < 8; r++)
                #pragma unroll
                for (int q = 0; q < 4; q++)
                    *(ull*)&stage[(r0+r)*128 + cg*8 + 2*q] = acc[r][q];
        }
        __syncthreads();
        #pragma unroll
        for (int rr = 0; rr < 8; rr++) {
            int lrow = w*8 + rr;
            int n = nbase + half*64 + lrow;
            float4 nv4 = *(const float4*)&stage[lrow*128 + lane*4];
            float4 h4 = make_float4(0.f,0.f,0.f,0.f);
            float den = 1.f;
            size_t idx = ((size_t)(b*NN) + n)*CC + lane*4;
            if (n < NN) { h4 = *(const float4*)&g_h[idx]; den = g_den[b*NN+n]; }
            float r_ = 1.0f / den;
            float v0 = nv4.x*r_ + h4.x, v1 = nv4.y*r_ + h4.y;
            float v2 = nv4.z*r_ + h4.z, v3 = nv4.w*r_ + h4.w;
            float s  = v0+v1+v2+v3;
            float s2 = v0*v0+v1*v1+v2*v2+v3*v3;
            #pragma unroll
            for (int o = 16; o; o >>= 1) {
                s  += __shfl_xor_sync(0xffffffffu, s,  o);
                s2 += __shfl_xor_sync(0xffffffffu, s2, o);
            }
            float mu  = s * (1.0f/128.0f);
            float var = s2 * (1.0f/128.0f) - mu*mu;
            float is  = rsqrtf(var + 1e-5f);
            if (n < NN) {
                float4 g4 = *(const float4*)&ln_g[layer*CC + lane*4];
                float4 b4 = *(const float4*)&ln_b[layer*CC + lane*4];
                float4 o4;
                o4.x = (v0-mu)*is*g4.x + b4.x;
                o4.y = (v1-mu)*is*g4.y + b4.y;
                o4.z = (v2-mu)*is*g4.z + b4.z;
                o4.w = (v3-mu)*is*g4.w + b4.w;
                *(float4*)&g_h[idx] = o4;
            }
        }
    }
}

// ---------------- regression head ----------------
__global__ void k_reg(const float* __restrict__ reg_w,
                      const float* __restrict__ reg_b,
                      float* __restrict__ out)
{
    int b = blockIdx.y, t = threadIdx.x;
    __shared__ float rw[PP*2*CC];
    __shared__ float st[128*33];
    for (int i = t; i < PP*2*CC; i += 128) rw[i] = reg_w[i];
    int nbase = blockIdx.x*128;
    float acc[PP];
    #pragma unroll
    for (int p = 0; p < PP; p++) acc[p] = 0.f;
    for (int src = 0; src < 2; src++) {
        const float* S = src ? g_h : g_skip;
        for (int c0 = 0; c0 < CC; c0 += 32) {
            __syncthreads();
            #pragma unroll
            for (int k = 0; k < 32; k++) {
                int lin = t + k*128;
                int rr = lin >> 5, cc = lin & 31;
                int n = nbase + rr;
                st[rr*33+cc] = (n < NN) ? S[((size_t)(b*NN) + n)*CC + c0 + cc] : 0.f;
            }
            __syncthreads();
            #pragma unroll
            for (int cc = 0; cc < 32; cc++) {
                float v = st[t*33+cc];
                #pragma unroll
                for (int p = 0; p < PP; p++)
                    acc[p] += v * rw[p*(2*CC) + src*CC + c0 + cc];
            }
        }
    }
    int n = nbase + t;
    if (n < NN) {
        #pragma unroll
        for (int p = 0; p < PP; p++)
            out[((size_t)(b*PP) + p)*NN + n] = acc[p] + reg_b[p];
    }
}

// ---------------- launcher ----------------
extern "C" void kernel_launch(void* const* d_in, const int* in_sizes, int n_in,
                              void* d_out, int out_size)
{
    const float* x        = (const float*)d_in[0];
    const float* xmark    = (const float*)d_in[1];
    const float* node_emb = (const float*)d_in[2];
    const float* time_tab = (const float*)d_in[3];
    const float* week_tab = (const float*)d_in[4];
    const float* input_w  = (const float*)d_in[5];
    const float* input_b  = (const float*)d_in[6];
    const float* w1_w     = (const float*)d_in[7];
    const float* w1_b     = (const float*)d_in[8];
    const float* w2_w     = (const float*)d_in[9];
    const float* w2_b     = (const float*)d_in[10];
    const float* in_w     = (const float*)d_in[11];
    const float* in_b     = (const float*)d_in[12];
    const float* out_w    = (const float*)d_in[13];
    const float* out_b    = (const float*)d_in[14];
    const float* ln_g     = (const float*)d_in[15];
    const float* ln_b     = (const float*)d_in[16];
    const float* reg_w    = (const float*)d_in[17];
    const float* reg_b    = (const float*)d_in[18];
    const float* proj     = (const float*)d_in[19];
    float* out = (float*)d_out;

    cudaFuncSetAttribute(k_num,    cudaFuncAttributeMaxDynamicSharedMemorySize, SMEM_NUM);
    cudaFuncSetAttribute(k_gatekv, cudaFuncAttributeMaxDynamicSharedMemorySize, SMEM_GATE);

    dim3 gBN(NBLK, BB);

    k_const<<<BB, 128>>>(xmark, time_tab, week_tab, input_w, input_b,
                         w1_w, w1_b, w2_w, w2_b, proj);
    k_node<<<(NN + 255)/256, 256>>>(node_emb, w1_w, w2_w);
    k_colmax<<<MM, 256>>>(proj);
    k_stab<<<BB, 64>>>();
    k_phi<<<gBN, 128>>>(proj);
    k_input<<<gBN, 128>>>(x, input_w, node_emb);
    k_ksum<<<dim3(NCH, BB), 256>>>();
    k_ksumred<<<BB, 64>>>();
    k_den<<<gBN, 128>>>();

    for (int l = 0; l < LL; l++) {
        k_gatekv<<<gBN, 512, SMEM_GATE>>>(in_w, in_b, out_w, out_b, l);
        k_kvred<<<dim3(32, BB), 256>>>();
        k_num<<<gBN, 256, SMEM_NUM>>>(ln_g, ln_b, l);
    }
    k_reg<<<gBN, 128>>>(reg_w, reg_b, out);
}